// round 14
// baseline (speedup 1.0000x reference)
#include <cuda_runtime.h>
#include <cuda_bf16.h>
#include <math.h>
#include <stdint.h>

#define HIDDEN   256
#define NQ       300
#define BS       2
#define LVLS     4
#define NHEADS   8
#define TOTALPIX 21760
#define BQ       (BS*NQ)          // 600
#define NROWS    (LVLS*BS*NQ)     // 2400
#define XCOLS    3136
#define KSPLIT1  7                // 3136 = 7*448

// ---------------- scratch (static device globals; no runtime alloc) ----------
__device__ float g_gate[BQ * NHEADS * HIDDEN];   // 600 x 2048
__device__ float g_proj[BS * TOTALPIX * 64];     // projected memory
__device__ float g_X  [NROWS * XCOLS];           // MLP input rows (permuted cols)
__device__ float g_w1p[XCOLS * 256];             // w1 with permuted rows
__device__ float g_P  [KSPLIT1 * NROWS * 256];   // split-K partials (reused)
__device__ float g_H1 [NROWS * 256];
__device__ float g_H2 [NROWS * 512];
__device__ float g_H3 [NROWS * 512];
__device__ float g_pts[NROWS * 16];

__device__ __constant__ int c_dim[4]   = {128, 64, 32, 16};
__device__ __constant__ int c_start[4] = {0, 16384, 20480, 21504};

// ---------------- shared geometry helper (roi_align sampling) ----------------
__device__ __forceinline__ void sample4(float sx, float sy, float bw, float bh,
                                        int W, int si, int sj,
                                        int idx[4], float wt[4]) {
    float Wf = (float)W;
    float ty = (float)(si >> 1) + 0.25f + 0.5f * (float)(si & 1);
    float tx = (float)(sj >> 1) + 0.25f + 0.5f * (float)(sj & 1);
    float y = sy + bh * ty;
    float x = sx + bw * tx;
    bool valid = (y >= -1.f) && (y <= Wf) && (x >= -1.f) && (x <= Wf);
    float yc = fminf(fmaxf(y, 0.f), Wf - 1.f);
    float xc = fminf(fmaxf(x, 0.f), Wf - 1.f);
    float y0 = fminf(floorf(yc), Wf - 2.f);
    float x0 = fminf(floorf(xc), Wf - 2.f);
    float ly = yc - y0, lx = xc - x0;
    int yi = (int)y0, xi = (int)x0;
    int p = yi * W + xi;
    float vm = valid ? 0.25f : 0.f;
    float oy = 1.f - ly, ox = 1.f - lx;
    idx[0] = p;         wt[0] = oy * ox * vm;
    idx[1] = p + 1;     wt[1] = oy * lx * vm;
    idx[2] = p + W;     wt[2] = ly * ox * vm;
    idx[3] = p + W + 1; wt[3] = ly * lx * vm;
}

__device__ __forceinline__ void box_geom(const float* __restrict__ r6, int W,
                                         float& sx, float& sy, float& bw, float& bh) {
    float Wf = (float)W;
    float cx = r6[0], cy = r6[1];
    float x1 = fminf(fmaxf(cx - r6[2], 0.f), 1.f) * Wf;
    float y1 = fminf(fmaxf(cy - r6[3], 0.f), 1.f) * Wf;
    float x2 = fminf(fmaxf(cx + r6[4], 0.f), 1.f) * Wf;
    float y2 = fminf(fmaxf(cy + r6[5], 0.f), 1.f) * Wf;
    sx = x1 - 0.5f; sy = y1 - 0.5f;
    bw = (x2 - x1) / 7.f; bh = (y2 - y1) / 7.f;
}

// ================== shared mma building blocks ================================
__device__ __forceinline__ void cvt8(float4 u, float4 v, uint4& hi, uint4& lo) {
    __nv_bfloat162 h0 = __floats2bfloat162_rn(u.x, u.y);
    __nv_bfloat162 h1 = __floats2bfloat162_rn(u.z, u.w);
    __nv_bfloat162 h2 = __floats2bfloat162_rn(v.x, v.y);
    __nv_bfloat162 h3 = __floats2bfloat162_rn(v.z, v.w);
    hi.x = *(uint32_t*)&h0; hi.y = *(uint32_t*)&h1;
    hi.z = *(uint32_t*)&h2; hi.w = *(uint32_t*)&h3;
    __nv_bfloat162 l0 = __floats2bfloat162_rn(u.x - __bfloat162float(h0.x),
                                              u.y - __bfloat162float(h0.y));
    __nv_bfloat162 l1 = __floats2bfloat162_rn(u.z - __bfloat162float(h1.x),
                                              u.w - __bfloat162float(h1.y));
    __nv_bfloat162 l2 = __floats2bfloat162_rn(v.x - __bfloat162float(h2.x),
                                              v.y - __bfloat162float(h2.y));
    __nv_bfloat162 l3 = __floats2bfloat162_rn(v.z - __bfloat162float(h3.x),
                                              v.w - __bfloat162float(h3.y));
    lo.x = *(uint32_t*)&l0; lo.y = *(uint32_t*)&l1;
    lo.z = *(uint32_t*)&l2; lo.w = *(uint32_t*)&l3;
}

__device__ __forceinline__ void ldsm4(uint32_t r[4], uint32_t addr) {
    asm volatile("ldmatrix.sync.aligned.m8n8.x4.shared.b16 {%0,%1,%2,%3}, [%4];"
                 : "=r"(r[0]), "=r"(r[1]), "=r"(r[2]), "=r"(r[3]) : "r"(addr));
}
__device__ __forceinline__ void ldsm4t(uint32_t r[4], uint32_t addr) {
    asm volatile("ldmatrix.sync.aligned.m8n8.x4.trans.shared.b16 {%0,%1,%2,%3}, [%4];"
                 : "=r"(r[0]), "=r"(r[1]), "=r"(r[2]), "=r"(r[3]) : "r"(addr));
}
__device__ __forceinline__ void mma_bf16(float c[4], const uint32_t a[4], const uint32_t* b) {
    asm volatile(
        "mma.sync.aligned.m16n8k16.row.col.f32.bf16.bf16.f32 "
        "{%0,%1,%2,%3},{%4,%5,%6,%7},{%8,%9},{%0,%1,%2,%3};"
        : "+f"(c[0]), "+f"(c[1]), "+f"(c[2]), "+f"(c[3])
        : "r"(a[0]), "r"(a[1]), "r"(a[2]), "r"(a[3]), "r"(b[0]), "r"(b[1]));
}

// ================== narrow GEMM: BM=64 BN=64 (round-4 proven, unchanged) =====
template <int EPI>   // 0 none, 1 relu, 2 sigmoid, 3 tanh
__global__ __launch_bounds__(128, 4)
void bf_gemm(const float* __restrict__ A, const float* __restrict__ B,
             const float* __restrict__ bias, float* __restrict__ C,
             int M, int N, int K, int kSplit) {
    __shared__ __align__(16) unsigned char sm[16384];
    uint32_t sbase = (uint32_t)__cvta_generic_to_shared(sm);

    int bn0 = blockIdx.x * 64, bm0 = blockIdx.y * 64;
    int kS = blockIdx.z * kSplit;
    C += (size_t)blockIdx.z * M * N;

    int tid = threadIdx.x, warp = tid >> 5, lane = tid & 31;
    int wm0 = (warp & 1) * 32, wn0 = (warp >> 1) * 32;
    int lq = lane >> 2, lr = lane & 3;

    int aM[2], aG[2], bK[2], bNg[2];
#pragma unroll
    for (int u = 0; u < 2; u++) {
        int e = tid + 128 * u;
        aM[u] = e >> 2; aG[u] = e & 3;
        bK[u] = e >> 3; bNg[u] = e & 7;
    }

    int matSel = lane >> 3;
    int rowA = (lane & 7) + ((matSel & 1) << 3);
    int cbitA = matSel >> 1;
    int rA0 = wm0 + rowA, rA1 = wm0 + 16 + rowA;
    int swzA0 = (rA0 >> 1) & 3, swzA1 = (rA1 >> 1) & 3;
    uint32_t aRow0 = sbase + rA0 * 64;
    uint32_t aRow1 = sbase + rA1 * 64;

    int kr0 = (lane & 7) + ((matSel & 1) << 3);
    int cb0 = (wn0 >> 3) + (matSel >> 1);
    int cb2 = cb0 + 2;
    uint32_t bOff0 = sbase + 8192 + kr0 * 128 + ((uint32_t)(cb0 ^ (kr0 & 7)) << 4);
    uint32_t bOff2 = sbase + 8192 + kr0 * 128 + ((uint32_t)(cb2 ^ (kr0 & 7)) << 4);

    float acc[2][4][4];
#pragma unroll
    for (int i = 0; i < 2; i++)
#pragma unroll
        for (int j = 0; j < 4; j++)
#pragma unroll
            for (int k = 0; k < 4; k++) acc[i][j][k] = 0.f;

    float4 pa[2][2], pb[2][2];
    const float4 z4 = make_float4(0.f, 0.f, 0.f, 0.f);

    auto loadTile = [&](int t) {
#pragma unroll
        for (int u = 0; u < 2; u++) {
            int gm = bm0 + aM[u];
            int ka = kS + t * 32 + aG[u] * 8;
            if (gm < M) {
                const float* p = A + (size_t)gm * K + ka;
                pa[u][0] = *(const float4*)p; pa[u][1] = *(const float4*)(p + 4);
            } else { pa[u][0] = z4; pa[u][1] = z4; }
            int gn = bn0 + bNg[u] * 8;
            int kb = kS + t * 32 + bK[u];
            if (gn < N) {
                const float* p = B + (size_t)kb * N + gn;
                pb[u][0] = *(const float4*)p; pb[u][1] = *(const float4*)(p + 4);
            } else { pb[u][0] = z4; pb[u][1] = z4; }
        }
    };

    loadTile(0);
    int T = kSplit / 32;
    for (int t = 0; t < T; t++) {
#pragma unroll
        for (int u = 0; u < 2; u++) {
            uint4 hi, lo;
            cvt8(pa[u][0], pa[u][1], hi, lo);
            uint32_t off = aM[u] * 64 + ((uint32_t)(aG[u] ^ ((aM[u] >> 1) & 3)) << 4);
            *(uint4*)(sm + off) = hi;
            *(uint4*)(sm + 4096 + off) = lo;
            cvt8(pb[u][0], pb[u][1], hi, lo);
            off = 8192 + bK[u] * 128 + ((uint32_t)(bNg[u] ^ (bK[u] & 7)) << 4);
            *(uint4*)(sm + off) = hi;
            *(uint4*)(sm + 4096 + off) = lo;
        }
        __syncthreads();

        if (t + 1 < T) loadTile(t + 1);

#pragma unroll
        for (int s = 0; s < 2; s++) {
            uint32_t aH0[4], aL0[4], aH1[4], aL1[4];
            uint32_t ad0 = aRow0 + ((uint32_t)((2 * s + cbitA) ^ swzA0) << 4);
            uint32_t ad1 = aRow1 + ((uint32_t)((2 * s + cbitA) ^ swzA1) << 4);
            ldsm4(aH0, ad0); ldsm4(aL0, ad0 + 4096);
            ldsm4(aH1, ad1); ldsm4(aL1, ad1 + 4096);
            uint32_t bH01[4], bL01[4], bH23[4], bL23[4];
            uint32_t bd0 = bOff0 + s * 2048, bd2 = bOff2 + s * 2048;
            ldsm4t(bH01, bd0); ldsm4t(bL01, bd0 + 4096);
            ldsm4t(bH23, bd2); ldsm4t(bL23, bd2 + 4096);

#pragma unroll
            for (int mf = 0; mf < 2; mf++) {
                const uint32_t* aH = mf ? aH1 : aH0;
                const uint32_t* aL = mf ? aL1 : aL0;
#pragma unroll
                for (int nf = 0; nf < 4; nf++) {
                    const uint32_t* bH = (nf < 2) ? &bH01[(nf & 1) * 2] : &bH23[(nf & 1) * 2];
                    const uint32_t* bL = (nf < 2) ? &bL01[(nf & 1) * 2] : &bL23[(nf & 1) * 2];
                    mma_bf16(acc[mf][nf], aL, bH);
                    mma_bf16(acc[mf][nf], aH, bL);
                    mma_bf16(acc[mf][nf], aH, bH);
                }
            }
        }
        __syncthreads();
    }

#pragma unroll
    for (int mf = 0; mf < 2; mf++)
#pragma unroll
        for (int nf = 0; nf < 4; nf++)
#pragma unroll
            for (int ci = 0; ci < 4; ci++) {
                int m = bm0 + wm0 + mf * 16 + lq + ((ci >= 2) ? 8 : 0);
                int n = bn0 + wn0 + nf * 8 + lr * 2 + (ci & 1);
                if (m >= M || n >= N) continue;
                float v = acc[mf][nf][ci] + (bias ? bias[n] : 0.f);
                if (EPI == 1) v = fmaxf(v, 0.f);
                else if (EPI == 2) v = 1.f / (1.f + expf(-v));
                else if (EPI == 3) v = tanhf(v);
                C[(size_t)m * N + n] = v;
            }
}

// ================== wide GEMM: BM=64 BN=128, warp tile 32x64 =================
__global__ __launch_bounds__(128, 2)
void bf_gemm_w(const float* __restrict__ A, const float* __restrict__ B,
               float* __restrict__ C, int M, int N, int K, int kSplit) {
    __shared__ __align__(16) unsigned char sm[24576];
    uint32_t sbase = (uint32_t)__cvta_generic_to_shared(sm);

    int bn0 = blockIdx.x * 128, bm0 = blockIdx.y * 64;
    int kS = blockIdx.z * kSplit;
    C += (size_t)blockIdx.z * M * N;

    int tid = threadIdx.x, warp = tid >> 5, lane = tid & 31;
    int wm0 = (warp & 1) * 32, wn0 = (warp >> 1) * 64;
    int lq = lane >> 2, lr = lane & 3;

    int aM[2], aG[2];
#pragma unroll
    for (int u = 0; u < 2; u++) {
        int e = tid + 128 * u;
        aM[u] = e >> 2; aG[u] = e & 3;
    }
    int bKr[4], bC[4];
#pragma unroll
    for (int u = 0; u < 4; u++) {
        int e = tid + 128 * u;
        bKr[u] = e >> 4; bC[u] = e & 15;
    }

    int matSel = lane >> 3;
    int rowA = (lane & 7) + ((matSel & 1) << 3);
    int cbitA = matSel >> 1;
    int rA0 = wm0 + rowA, rA1 = wm0 + 16 + rowA;
    int swzA0 = (rA0 >> 1) & 3, swzA1 = (rA1 >> 1) & 3;
    uint32_t aRow0 = sbase + rA0 * 64;
    uint32_t aRow1 = sbase + rA1 * 64;

    int kr0 = (lane & 7) + ((matSel & 1) << 3);
    int msHalf = matSel >> 1;
    uint32_t bOffG[4];
#pragma unroll
    for (int g = 0; g < 4; g++) {
        int cb = (wn0 >> 3) + 2 * g + msHalf;
        bOffG[g] = sbase + 8192 + kr0 * 256 + ((uint32_t)(cb ^ (kr0 & 7)) << 4);
    }

    float acc[2][8][4];
#pragma unroll
    for (int i = 0; i < 2; i++)
#pragma unroll
        for (int j = 0; j < 8; j++)
#pragma unroll
            for (int k = 0; k < 4; k++) acc[i][j][k] = 0.f;

    float4 pa[2][2], pb[4][2];
    const float4 z4 = make_float4(0.f, 0.f, 0.f, 0.f);

    auto loadTile = [&](int t) {
#pragma unroll
        for (int u = 0; u < 2; u++) {
            int gm = bm0 + aM[u];
            int ka = kS + t * 32 + aG[u] * 8;
            if (gm < M) {
                const float* p = A + (size_t)gm * K + ka;
                pa[u][0] = *(const float4*)p; pa[u][1] = *(const float4*)(p + 4);
            } else { pa[u][0] = z4; pa[u][1] = z4; }
        }
#pragma unroll
        for (int u = 0; u < 4; u++) {
            int gn = bn0 + bC[u] * 8;
            int kb = kS + t * 32 + bKr[u];
            if (gn < N) {
                const float* p = B + (size_t)kb * N + gn;
                pb[u][0] = *(const float4*)p; pb[u][1] = *(const float4*)(p + 4);
            } else { pb[u][0] = z4; pb[u][1] = z4; }
        }
    };

    loadTile(0);
    int T = kSplit / 32;
    for (int t = 0; t < T; t++) {
#pragma unroll
        for (int u = 0; u < 2; u++) {
            uint4 hi, lo;
            cvt8(pa[u][0], pa[u][1], hi, lo);
            uint32_t off = aM[u] * 64 + ((uint32_t)(aG[u] ^ ((aM[u] >> 1) & 3)) << 4);
            *(uint4*)(sm + off) = hi;
            *(uint4*)(sm + 4096 + off) = lo;
        }
#pragma unroll
        for (int u = 0; u < 4; u++) {
            uint4 hi, lo;
            cvt8(pb[u][0], pb[u][1], hi, lo);
            uint32_t off = 8192 + bKr[u] * 256 + ((uint32_t)(bC[u] ^ (bKr[u] & 7)) << 4);
            *(uint4*)(sm + off) = hi;
            *(uint4*)(sm + 8192 + off) = lo;
        }
        __syncthreads();

        if (t + 1 < T) loadTile(t + 1);

#pragma unroll
        for (int s = 0; s < 2; s++) {
            uint32_t aH0[4], aL0[4], aH1[4], aL1[4];
            uint32_t ad0 = aRow0 + ((uint32_t)((2 * s + cbitA) ^ swzA0) << 4);
            uint32_t ad1 = aRow1 + ((uint32_t)((2 * s + cbitA) ^ swzA1) << 4);
            ldsm4(aH0, ad0); ldsm4(aL0, ad0 + 4096);
            ldsm4(aH1, ad1); ldsm4(aL1, ad1 + 4096);
            uint32_t bH[4][4], bL[4][4];
#pragma unroll
            for (int g = 0; g < 4; g++) {
                uint32_t bd = bOffG[g] + s * 4096;
                ldsm4t(bH[g], bd);
                ldsm4t(bL[g], bd + 8192);
            }
#pragma unroll
            for (int mf = 0; mf < 2; mf++) {
                const uint32_t* aH = mf ? aH1 : aH0;
                const uint32_t* aL = mf ? aL1 : aL0;
#pragma unroll
                for (int nf = 0; nf < 8; nf++) {
                    int g = nf >> 1;
                    const uint32_t* pbH = &bH[g][(nf & 1) * 2];
                    const uint32_t* pbL = &bL[g][(nf & 1) * 2];
                    mma_bf16(acc[mf][nf], aL, pbH);
                    mma_bf16(acc[mf][nf], aH, pbL);
                    mma_bf16(acc[mf][nf], aH, pbH);
                }
            }
        }
        __syncthreads();
    }

#pragma unroll
    for (int mf = 0; mf < 2; mf++)
#pragma unroll
        for (int nf = 0; nf < 8; nf++)
#pragma unroll
            for (int ci = 0; ci < 4; ci++) {
                int m = bm0 + wm0 + mf * 16 + lq + ((ci >= 2) ? 8 : 0);
                int n = bn0 + wn0 + nf * 8 + lr * 2 + (ci & 1);
                if (m >= M || n >= N) continue;
                C[(size_t)m * N + n] = acc[mf][nf][ci];
            }
}

// ---------------- w1 row permutation ------------------------------------------
__global__ __launch_bounds__(256)
void permute_w1_kernel(const float* __restrict__ w1, float* __restrict__ w1p) {
    int k = blockIdx.x;
    int d = k / 49, bin = k - d * 49;
    int kp = bin * 64 + d;
    w1p[(size_t)kp * 256 + threadIdx.x] = w1[(size_t)k * 256 + threadIdx.x];
}

// ---------------- generic split-K combine: H = epi(sum_z P_z + bias) ----------
template <int EPI, int Z>
__global__ __launch_bounds__(256)
void combine_k(const float* __restrict__ P, const float* __restrict__ bias,
               float* __restrict__ H, int total, int nMask) {
    int i = blockIdx.x * 256 + threadIdx.x;
    if (i < total) {
        float v = bias[i & nMask];
#pragma unroll
        for (int z = 0; z < Z; z++)
            v += P[(size_t)z * total + i];
        if (EPI == 1) v = fmaxf(v, 0.f);
        else if (EPI == 3) v = tanhf(v);
        H[i] = v;
    }
}

// ---------------- build X rows: per-bin deduped gathers ----------------------
__global__ __launch_bounds__(256)
void build_x_kernel(const float* __restrict__ ref, const float* __restrict__ p1_b) {
    int blk = blockIdx.x;                 // lvl*600 + b*300 + q
    int lvl = blk / BQ;
    int rem = blk - lvl * BQ;
    int b = rem / NQ;
    int q = rem - b * NQ;
    int W = c_dim[lvl];
    int start = c_start[lvl];
    const float* r6 = ref + ((size_t)(b * NQ + q) * LVLS + lvl) * 6;
    float sx, sy, bw, bh;
    box_geom(r6, W, sx, sy, bw, bh);

    __shared__ int   sIdx[196][4];
    __shared__ float sW[196][4];
    __shared__ int   sBI[49][16];
    __shared__ float sBW[49][16];
    __shared__ int   sCnt[49];
    int tid = threadIdx.x;
    if (tid < 196) {
        int si = tid / 14, sj = tid - si * 14;
        int idx4[4]; float wt4[4];
        sample4(sx, sy, bw, bh, W, si, sj, idx4, wt4);
#pragma unroll
        for (int k = 0; k < 4; k++) { sIdx[tid][k] = idx4[k]; sW[tid][k] = wt4[k]; }
    }
    __syncthreads();

    // per-bin dedup: 49 threads merge 16 (idx,w) entries into compact lists
    if (tid < 49) {
        int h = tid / 7, w_ = tid - h * 7;
        int cnt = 0;
#pragma unroll
        for (int s2 = 0; s2 < 4; s2++) {
            int s = (2 * h + (s2 >> 1)) * 14 + 2 * w_ + (s2 & 1);
#pragma unroll
            for (int cr = 0; cr < 4; cr++) {
                int idx = sIdx[s][cr];
                float w = sW[s][cr];
                int j = 0;
                for (; j < cnt; j++)
                    if (sBI[tid][j] == idx) { sBW[tid][j] += w; break; }
                if (j == cnt) { sBI[tid][cnt] = idx; sBW[tid][cnt] = w; cnt++; }
            }
        }
        sCnt[tid] = cnt;
    }
    __syncthreads();

    int sub = tid >> 4;                    // 0..15 (bin subgroup)
    int d4  = (tid & 15) * 4;              // channel base
    const float* projB = g_proj + ((size_t)b * TOTALPIX + start) * 64 + d4;
    float4 bias4 = *(const float4*)(p1_b + d4);
    float* Xrow = g_X + (size_t)blk * XCOLS;
    for (int bin = sub; bin < 49; bin += 16) {
        int cnt = sCnt[bin];
        float4 acc = make_float4(0.f, 0.f, 0.f, 0.f);
        for (int e = 0; e < cnt; e++) {
            float w = sBW[bin][e];
            if (w != 0.f) {
                int idx = sBI[bin][e];
                const float4 v = *(const float4*)(projB + (size_t)idx * 64);
                acc.x += w * v.x; acc.y += w * v.y;
                acc.z += w * v.z; acc.w += w * v.w;
            }
        }
        float4 o;
        o.x = fmaxf(acc.x + bias4.x, 0.f);
        o.y = fmaxf(acc.y + bias4.y, 0.f);
        o.z = fmaxf(acc.z + bias4.z, 0.f);
        o.w = fmaxf(acc.w + bias4.w, 0.f);
        *(float4*)(Xrow + bin * 64 + d4) = o;
    }
}

// ---------------- finalize: dedup + compact gathers + float4 loads -----------
__global__ __launch_bounds__(256)
void finalize_kernel(const float* __restrict__ memory, const float* __restrict__ ref,
                     const float* __restrict__ a2w, const float* __restrict__ a2b,
                     float* __restrict__ out) {
    int bq = blockIdx.x;                   // b*300 + q
    int b = bq / NQ;
    int tid = threadIdx.x;

    __shared__ float qe_s[32][HIDDEN];     // 32 KB
    __shared__ float wArr[2048];           // 8 KB
    __shared__ unsigned short iArr[2048];  // 4 KB
    __shared__ unsigned short cntArr[64];
    __shared__ float logits[32];
    __shared__ float wgt[32];

    for (int e = tid; e < 2048; e += 256) {
        int lvl = e >> 9;
        int head = (e >> 6) & 7;
        int bc = (e >> 4) & 3;
        int sm = (e >> 2) & 3;
        int cr = e & 3;
        int W = c_dim[lvl];
        int start = c_start[lvl];
        const float* r6 = ref + ((size_t)bq * LVLS + lvl) * 6;
        float sx, sy, bw, bh;
        box_geom(r6, W, sx, sy, bw, bh);

        int row = lvl * BQ + bq;
        float gx = g_pts[row * 16 + 2 * head];
        float gy = g_pts[row * 16 + 2 * head + 1];
        float ix = ((gx + 1.f) * 7.f - 1.f) * 0.5f;
        float iy = ((gy + 1.f) * 7.f - 1.f) * 0.5f;
        float bxf = floorf(ix), byf = floorf(iy);
        float lx = ix - bxf, ly = iy - byf;
        int dby = bc >> 1, dbx = bc & 1;
        int bi = (int)byf + dby, bj = (int)bxf + dbx;
        float wb = (dby ? ly : 1.f - ly) * (dbx ? lx : 1.f - lx);
        if (bi < 0 || bi > 6 || bj < 0 || bj > 6) wb = 0.f;
        int si = 2 * bi + (sm >> 1);
        int sj = 2 * bj + (sm & 1);
        int idx4[4]; float wt4[4];
        sample4(sx, sy, bw, bh, W, si, sj, idx4, wt4);
        wArr[e] = wb * wt4[cr];
        iArr[e] = (unsigned short)(b * TOTALPIX + start + idx4[cr]);
    }
    __syncthreads();

    // dedup + compact per 32-entry half of each (lvl,head) group
    {
        int warp = tid >> 5, lane = tid & 31;
        for (int h = warp; h < 64; h += 8) {
            int e = h * 32 + lane;
            unsigned idx = iArr[e];
            float w = wArr[e];
            unsigned mask = __match_any_sync(0xffffffffu, idx);
            int leader = __ffs(mask) - 1;
            float tot = 0.f;
#pragma unroll
            for (int bb = 0; bb < 32; bb++) {
                float wb2 = __shfl_sync(0xffffffffu, w, bb);
                if ((mask >> bb) & 1) tot += wb2;
            }
            float wn = (lane == leader) ? tot : 0.f;
            unsigned bal = __ballot_sync(0xffffffffu, wn != 0.f);
            int pos = __popc(bal & ((1u << lane) - 1));
            if (wn != 0.f) {
                wArr[h * 32 + pos] = wn;
                iArr[h * 32 + pos] = (unsigned short)idx;
            }
            if (lane == 0) cntArr[h] = (unsigned short)__popc(bal);
        }
    }
    __syncthreads();

    const float* gateRow = g_gate + (size_t)bq * (NHEADS * HIDDEN);
    int g64 = tid >> 6;                    // 0..3
    int c4 = (tid & 63) * 4;               // channel base
    for (int lh = g64; lh < 32; lh += 4) {
        float4 acc = make_float4(0.f, 0.f, 0.f, 0.f);
        int eb = lh << 6;
        int n0 = cntArr[2 * lh], n1 = cntArr[2 * lh + 1];
        for (int e = 0; e < n0; e++) {
            float w = wArr[eb + e];
            const float4 v = *(const float4*)(memory + (size_t)iArr[eb + e] * HIDDEN + c4);
            acc.x += w * v.x; acc.y += w * v.y;
            acc.z += w * v.z; acc.w += w * v.w;
        }
        for (int e = 0; e < n1; e++) {
            float w = wArr[eb + 32 + e];
            const float4 v = *(const float4*)(memory + (size_t)iArr[eb + 32 + e] * HIDDEN + c4);
            acc.x += w * v.x; acc.y += w * v.y;
            acc.z += w * v.z; acc.w += w * v.w;
        }
        const float4 gt = *(const float4*)(gateRow + (lh & 7) * HIDDEN + c4);
        qe_s[lh][c4 + 0] = acc.x * gt.x;
        qe_s[lh][c4 + 1] = acc.y * gt.y;
        qe_s[lh][c4 + 2] = acc.z * gt.z;
        qe_s[lh][c4 + 3] = acc.w * gt.w;
    }
    __syncthreads();

    int warp = tid >> 5, lane = tid & 31;
    for (int r = warp; r < 32; r += 8) {
        float s = 0.f;
#pragma unroll
        for (int c2 = lane; c2 < HIDDEN; c2 += 32) s += qe_s[r][c2] * a2w[c2];
#pragma unroll
        for (int o = 16; o; o >>= 1) s += __shfl_xor_sync(0xffffffffu, s, o);
        if (lane == 0) logits[r] = s + a2b[0];
    }
    __syncthreads();

    if (tid < 32) {
        float l = logits[tid];
        float mx = l;
#pragma unroll
        for (int o = 16; o; o >>= 1) mx = fmaxf(mx, __shfl_xor_sync(0xffffffffu, mx, o));
        float ex = expf(l - mx);
        float sum = ex;
#pragma unroll
        for (int o = 16; o; o >>= 1) sum += __shfl_xor_sync(0xffffffffu, sum, o);
        wgt[tid] = ex / sum;
    }
    __syncthreads();

    int c = tid;
    float o = 0.f;
#pragma unroll
    for (int r = 0; r < 32; r++) o += wgt[r] * qe_s[r][c];
    out[(size_t)bq * HIDDEN + c] = o;
}

// -----------------------------------------------------------------------------
static inline int cdiv(int a, int b) { return (a + b - 1) / b; }

extern "C" void kernel_launch(void* const* d_in, const int* in_sizes, int n_in,
                              void* d_out, int out_size) {
    const float* tgt    = (const float*)d_in[0];
    const float* memory = (const float*)d_in[1];
    const float* ref    = (const float*)d_in[2];
    const float* p1_w = (const float*)d_in[4];
    const float* p1_b = (const float*)d_in[5];
    const float* w1   = (const float*)d_in[6];
    const float* b1   = (const float*)d_in[7];
    const float* w2   = (const float*)d_in[8];
    const float* b2   = (const float*)d_in[9];
    const float* w3   = (const float*)d_in[10];
    const float* b3   = (const float*)d_in[11];
    const float* w4   = (const float*)d_in[12];
    const float* b4   = (const float*)d_in[13];
    const float* a1w  = (const float*)d_in[14];
    const float* a1b  = (const float*)d_in[15];
    const float* a2w  = (const float*)d_in[16];
    const float* a2b  = (const float*)d_in[17];
    float* out = (float*)d_out;

    float *gate, *proj, *X, *w1p, *P, *H1, *H2, *H3, *pts;
    cudaGetSymbolAddress((void**)&gate, g_gate);
    cudaGetSymbolAddress((void**)&proj, g_proj);
    cudaGetSymbolAddress((void**)&X,    g_X);
    cudaGetSymbolAddress((void**)&w1p,  g_w1p);
    cudaGetSymbolAddress((void**)&P,    g_P);
    cudaGetSymbolAddress((void**)&H1,   g_H1);
    cudaGetSymbolAddress((void**)&H2,   g_H2);
    cudaGetSymbolAddress((void**)&H3,   g_H3);
    cudaGetSymbolAddress((void**)&pts,  g_pts);

    dim3 t(128);
    // w1 row permutation (independent)
    permute_w1_kernel<<<XCOLS, 256>>>(w1, w1p);
    // gate = sigmoid(tgt @ attn1_w + attn1_b)   (600 x 2048, K=256)
    bf_gemm<2><<<dim3(32, 10, 1), t>>>(tgt, a1w, a1b, gate, BQ, 2048, 256, 256);
    // proj = memory @ p1_w                       (43520 x 64, K=256)
    bf_gemm<0><<<dim3(1, 680, 1), t>>>(memory, p1_w, nullptr, proj, BS * TOTALPIX, 64, 256, 256);
    // X rows via roi_align on projected memory (permuted col layout, deduped)
    build_x_kernel<<<NROWS, 256>>>(ref, p1_b);
    // MLP layer 1: WIDE tiles + split-K=7 (slabs of 448), then combine
    bf_gemm_w<<<dim3(2, 38, KSPLIT1), t>>>(X, w1p, P, NROWS, 256, XCOLS, 448);
    combine_k<1, KSPLIT1><<<cdiv(NROWS * 256, 256), 256>>>(P, b1, H1, NROWS * 256, 255);
    // MLP layer 2 (no split)
    bf_gemm<1><<<dim3(8, 38, 1), t>>>(H1, w2, b2, H2, NROWS, 512, 256, 256);
    // MLP layer 3: split-K=2, combine(relu)
    bf_gemm<0><<<dim3(8, 38, 2), t>>>(H2, w3, nullptr, P, NROWS, 512, 512, 256);
    combine_k<1, 2><<<cdiv(NROWS * 512, 256), 256>>>(P, b3, H3, NROWS * 512, 511);
    // MLP layer 4 (pts): split-K=4, combine(tanh)
    bf_gemm<0><<<dim3(1, 38, 4), t>>>(H3, w4, nullptr, P, NROWS, 16, 512, 128);
    combine_k<3, 4><<<cdiv(NROWS * 16, 256), 256>>>(P, b4, pts, NROWS * 16, 15);
    // grid-sample recompute + gate + softmax combine
    finalize_kernel<<<BQ, 256>>>(memory, ref, a2w, a2b, out);
}

// round 15
// speedup vs baseline: 1.0554x; 1.0554x over previous
#include <cuda_runtime.h>
#include <cuda_bf16.h>
#include <math.h>
#include <stdint.h>

#define HIDDEN   256
#define NQ       300
#define BS       2
#define LVLS     4
#define NHEADS   8
#define TOTALPIX 21760
#define BQ       (BS*NQ)          // 600
#define NROWS    (LVLS*BS*NQ)     // 2400
#define XCOLS    3136
#define KSPLIT1  7                // 3136 = 7*448

// ---------------- scratch (static device globals; no runtime alloc) ----------
__device__ float g_gate[BQ * NHEADS * HIDDEN];   // 600 x 2048
__device__ float g_proj[BS * TOTALPIX * 64];     // projected memory
__device__ float g_X  [NROWS * XCOLS];           // MLP input rows (permuted cols)
__device__ float g_w1p[XCOLS * 256];             // w1 with permuted rows
__device__ float g_P  [KSPLIT1 * NROWS * 256];   // split-K partials (reused)
__device__ float g_H1 [NROWS * 256];
__device__ float g_H2 [NROWS * 512];
__device__ float g_H3 [NROWS * 512];
__device__ float g_pts[NROWS * 16];

__device__ __constant__ int c_dim[4]   = {128, 64, 32, 16};
__device__ __constant__ int c_start[4] = {0, 16384, 20480, 21504};

// ---------------- shared geometry helper (roi_align sampling) ----------------
__device__ __forceinline__ void sample4(float sx, float sy, float bw, float bh,
                                        int W, int si, int sj,
                                        int idx[4], float wt[4]) {
    float Wf = (float)W;
    float ty = (float)(si >> 1) + 0.25f + 0.5f * (float)(si & 1);
    float tx = (float)(sj >> 1) + 0.25f + 0.5f * (float)(sj & 1);
    float y = sy + bh * ty;
    float x = sx + bw * tx;
    bool valid = (y >= -1.f) && (y <= Wf) && (x >= -1.f) && (x <= Wf);
    float yc = fminf(fmaxf(y, 0.f), Wf - 1.f);
    float xc = fminf(fmaxf(x, 0.f), Wf - 1.f);
    float y0 = fminf(floorf(yc), Wf - 2.f);
    float x0 = fminf(floorf(xc), Wf - 2.f);
    float ly = yc - y0, lx = xc - x0;
    int yi = (int)y0, xi = (int)x0;
    int p = yi * W + xi;
    float vm = valid ? 0.25f : 0.f;
    float oy = 1.f - ly, ox = 1.f - lx;
    idx[0] = p;         wt[0] = oy * ox * vm;
    idx[1] = p + 1;     wt[1] = oy * lx * vm;
    idx[2] = p + W;     wt[2] = ly * ox * vm;
    idx[3] = p + W + 1; wt[3] = ly * lx * vm;
}

__device__ __forceinline__ void box_geom(const float* __restrict__ r6, int W,
                                         float& sx, float& sy, float& bw, float& bh) {
    float Wf = (float)W;
    float cx = r6[0], cy = r6[1];
    float x1 = fminf(fmaxf(cx - r6[2], 0.f), 1.f) * Wf;
    float y1 = fminf(fmaxf(cy - r6[3], 0.f), 1.f) * Wf;
    float x2 = fminf(fmaxf(cx + r6[4], 0.f), 1.f) * Wf;
    float y2 = fminf(fmaxf(cy + r6[5], 0.f), 1.f) * Wf;
    sx = x1 - 0.5f; sy = y1 - 0.5f;
    bw = (x2 - x1) / 7.f; bh = (y2 - y1) / 7.f;
}

// ================== shared mma building blocks ================================
__device__ __forceinline__ void cvt8(float4 u, float4 v, uint4& hi, uint4& lo) {
    __nv_bfloat162 h0 = __floats2bfloat162_rn(u.x, u.y);
    __nv_bfloat162 h1 = __floats2bfloat162_rn(u.z, u.w);
    __nv_bfloat162 h2 = __floats2bfloat162_rn(v.x, v.y);
    __nv_bfloat162 h3 = __floats2bfloat162_rn(v.z, v.w);
    hi.x = *(uint32_t*)&h0; hi.y = *(uint32_t*)&h1;
    hi.z = *(uint32_t*)&h2; hi.w = *(uint32_t*)&h3;
    __nv_bfloat162 l0 = __floats2bfloat162_rn(u.x - __bfloat162float(h0.x),
                                              u.y - __bfloat162float(h0.y));
    __nv_bfloat162 l1 = __floats2bfloat162_rn(u.z - __bfloat162float(h1.x),
                                              u.w - __bfloat162float(h1.y));
    __nv_bfloat162 l2 = __floats2bfloat162_rn(v.x - __bfloat162float(h2.x),
                                              v.y - __bfloat162float(h2.y));
    __nv_bfloat162 l3 = __floats2bfloat162_rn(v.z - __bfloat162float(h3.x),
                                              v.w - __bfloat162float(h3.y));
    lo.x = *(uint32_t*)&l0; lo.y = *(uint32_t*)&l1;
    lo.z = *(uint32_t*)&l2; lo.w = *(uint32_t*)&l3;
}

__device__ __forceinline__ void ldsm4(uint32_t r[4], uint32_t addr) {
    asm volatile("ldmatrix.sync.aligned.m8n8.x4.shared.b16 {%0,%1,%2,%3}, [%4];"
                 : "=r"(r[0]), "=r"(r[1]), "=r"(r[2]), "=r"(r[3]) : "r"(addr));
}
__device__ __forceinline__ void ldsm4t(uint32_t r[4], uint32_t addr) {
    asm volatile("ldmatrix.sync.aligned.m8n8.x4.trans.shared.b16 {%0,%1,%2,%3}, [%4];"
                 : "=r"(r[0]), "=r"(r[1]), "=r"(r[2]), "=r"(r[3]) : "r"(addr));
}
__device__ __forceinline__ void mma_bf16(float c[4], const uint32_t a[4], const uint32_t* b) {
    asm volatile(
        "mma.sync.aligned.m16n8k16.row.col.f32.bf16.bf16.f32 "
        "{%0,%1,%2,%3},{%4,%5,%6,%7},{%8,%9},{%0,%1,%2,%3};"
        : "+f"(c[0]), "+f"(c[1]), "+f"(c[2]), "+f"(c[3])
        : "r"(a[0]), "r"(a[1]), "r"(a[2]), "r"(a[3]), "r"(b[0]), "r"(b[1]));
}

// ================== narrow GEMM: BM=64 BN=64 (round-4 proven, unchanged) =====
template <int EPI>   // 0 none, 1 relu, 2 sigmoid, 3 tanh
__global__ __launch_bounds__(128, 4)
void bf_gemm(const float* __restrict__ A, const float* __restrict__ B,
             const float* __restrict__ bias, float* __restrict__ C,
             int M, int N, int K, int kSplit) {
    __shared__ __align__(16) unsigned char sm[16384];
    uint32_t sbase = (uint32_t)__cvta_generic_to_shared(sm);

    int bn0 = blockIdx.x * 64, bm0 = blockIdx.y * 64;
    int kS = blockIdx.z * kSplit;
    C += (size_t)blockIdx.z * M * N;

    int tid = threadIdx.x, warp = tid >> 5, lane = tid & 31;
    int wm0 = (warp & 1) * 32, wn0 = (warp >> 1) * 32;
    int lq = lane >> 2, lr = lane & 3;

    int aM[2], aG[2], bK[2], bNg[2];
#pragma unroll
    for (int u = 0; u < 2; u++) {
        int e = tid + 128 * u;
        aM[u] = e >> 2; aG[u] = e & 3;
        bK[u] = e >> 3; bNg[u] = e & 7;
    }

    int matSel = lane >> 3;
    int rowA = (lane & 7) + ((matSel & 1) << 3);
    int cbitA = matSel >> 1;
    int rA0 = wm0 + rowA, rA1 = wm0 + 16 + rowA;
    int swzA0 = (rA0 >> 1) & 3, swzA1 = (rA1 >> 1) & 3;
    uint32_t aRow0 = sbase + rA0 * 64;
    uint32_t aRow1 = sbase + rA1 * 64;

    int kr0 = (lane & 7) + ((matSel & 1) << 3);
    int cb0 = (wn0 >> 3) + (matSel >> 1);
    int cb2 = cb0 + 2;
    uint32_t bOff0 = sbase + 8192 + kr0 * 128 + ((uint32_t)(cb0 ^ (kr0 & 7)) << 4);
    uint32_t bOff2 = sbase + 8192 + kr0 * 128 + ((uint32_t)(cb2 ^ (kr0 & 7)) << 4);

    float acc[2][4][4];
#pragma unroll
    for (int i = 0; i < 2; i++)
#pragma unroll
        for (int j = 0; j < 4; j++)
#pragma unroll
            for (int k = 0; k < 4; k++) acc[i][j][k] = 0.f;

    float4 pa[2][2], pb[2][2];
    const float4 z4 = make_float4(0.f, 0.f, 0.f, 0.f);

    auto loadTile = [&](int t) {
#pragma unroll
        for (int u = 0; u < 2; u++) {
            int gm = bm0 + aM[u];
            int ka = kS + t * 32 + aG[u] * 8;
            if (gm < M) {
                const float* p = A + (size_t)gm * K + ka;
                pa[u][0] = *(const float4*)p; pa[u][1] = *(const float4*)(p + 4);
            } else { pa[u][0] = z4; pa[u][1] = z4; }
            int gn = bn0 + bNg[u] * 8;
            int kb = kS + t * 32 + bK[u];
            if (gn < N) {
                const float* p = B + (size_t)kb * N + gn;
                pb[u][0] = *(const float4*)p; pb[u][1] = *(const float4*)(p + 4);
            } else { pb[u][0] = z4; pb[u][1] = z4; }
        }
    };

    loadTile(0);
    int T = kSplit / 32;
    for (int t = 0; t < T; t++) {
#pragma unroll
        for (int u = 0; u < 2; u++) {
            uint4 hi, lo;
            cvt8(pa[u][0], pa[u][1], hi, lo);
            uint32_t off = aM[u] * 64 + ((uint32_t)(aG[u] ^ ((aM[u] >> 1) & 3)) << 4);
            *(uint4*)(sm + off) = hi;
            *(uint4*)(sm + 4096 + off) = lo;
            cvt8(pb[u][0], pb[u][1], hi, lo);
            off = 8192 + bK[u] * 128 + ((uint32_t)(bNg[u] ^ (bK[u] & 7)) << 4);
            *(uint4*)(sm + off) = hi;
            *(uint4*)(sm + 4096 + off) = lo;
        }
        __syncthreads();

        if (t + 1 < T) loadTile(t + 1);

#pragma unroll
        for (int s = 0; s < 2; s++) {
            uint32_t aH0[4], aL0[4], aH1[4], aL1[4];
            uint32_t ad0 = aRow0 + ((uint32_t)((2 * s + cbitA) ^ swzA0) << 4);
            uint32_t ad1 = aRow1 + ((uint32_t)((2 * s + cbitA) ^ swzA1) << 4);
            ldsm4(aH0, ad0); ldsm4(aL0, ad0 + 4096);
            ldsm4(aH1, ad1); ldsm4(aL1, ad1 + 4096);
            uint32_t bH01[4], bL01[4], bH23[4], bL23[4];
            uint32_t bd0 = bOff0 + s * 2048, bd2 = bOff2 + s * 2048;
            ldsm4t(bH01, bd0); ldsm4t(bL01, bd0 + 4096);
            ldsm4t(bH23, bd2); ldsm4t(bL23, bd2 + 4096);

#pragma unroll
            for (int mf = 0; mf < 2; mf++) {
                const uint32_t* aH = mf ? aH1 : aH0;
                const uint32_t* aL = mf ? aL1 : aL0;
#pragma unroll
                for (int nf = 0; nf < 4; nf++) {
                    const uint32_t* bH = (nf < 2) ? &bH01[(nf & 1) * 2] : &bH23[(nf & 1) * 2];
                    const uint32_t* bL = (nf < 2) ? &bL01[(nf & 1) * 2] : &bL23[(nf & 1) * 2];
                    mma_bf16(acc[mf][nf], aL, bH);
                    mma_bf16(acc[mf][nf], aH, bL);
                    mma_bf16(acc[mf][nf], aH, bH);
                }
            }
        }
        __syncthreads();
    }

#pragma unroll
    for (int mf = 0; mf < 2; mf++)
#pragma unroll
        for (int nf = 0; nf < 4; nf++)
#pragma unroll
            for (int ci = 0; ci < 4; ci++) {
                int m = bm0 + wm0 + mf * 16 + lq + ((ci >= 2) ? 8 : 0);
                int n = bn0 + wn0 + nf * 8 + lr * 2 + (ci & 1);
                if (m >= M || n >= N) continue;
                float v = acc[mf][nf][ci] + (bias ? bias[n] : 0.f);
                if (EPI == 1) v = fmaxf(v, 0.f);
                else if (EPI == 2) v = 1.f / (1.f + expf(-v));
                else if (EPI == 3) v = tanhf(v);
                C[(size_t)m * N + n] = v;
            }
}

// ================== wide GEMM: BM=64 BN=128, warp tile 32x64 =================
__global__ __launch_bounds__(128, 2)
void bf_gemm_w(const float* __restrict__ A, const float* __restrict__ B,
               float* __restrict__ C, int M, int N, int K, int kSplit) {
    __shared__ __align__(16) unsigned char sm[24576];
    uint32_t sbase = (uint32_t)__cvta_generic_to_shared(sm);

    int bn0 = blockIdx.x * 128, bm0 = blockIdx.y * 64;
    int kS = blockIdx.z * kSplit;
    C += (size_t)blockIdx.z * M * N;

    int tid = threadIdx.x, warp = tid >> 5, lane = tid & 31;
    int wm0 = (warp & 1) * 32, wn0 = (warp >> 1) * 64;
    int lq = lane >> 2, lr = lane & 3;

    int aM[2], aG[2];
#pragma unroll
    for (int u = 0; u < 2; u++) {
        int e = tid + 128 * u;
        aM[u] = e >> 2; aG[u] = e & 3;
    }
    int bKr[4], bC[4];
#pragma unroll
    for (int u = 0; u < 4; u++) {
        int e = tid + 128 * u;
        bKr[u] = e >> 4; bC[u] = e & 15;
    }

    int matSel = lane >> 3;
    int rowA = (lane & 7) + ((matSel & 1) << 3);
    int cbitA = matSel >> 1;
    int rA0 = wm0 + rowA, rA1 = wm0 + 16 + rowA;
    int swzA0 = (rA0 >> 1) & 3, swzA1 = (rA1 >> 1) & 3;
    uint32_t aRow0 = sbase + rA0 * 64;
    uint32_t aRow1 = sbase + rA1 * 64;

    int kr0 = (lane & 7) + ((matSel & 1) << 3);
    int msHalf = matSel >> 1;
    uint32_t bOffG[4];
#pragma unroll
    for (int g = 0; g < 4; g++) {
        int cb = (wn0 >> 3) + 2 * g + msHalf;
        bOffG[g] = sbase + 8192 + kr0 * 256 + ((uint32_t)(cb ^ (kr0 & 7)) << 4);
    }

    float acc[2][8][4];
#pragma unroll
    for (int i = 0; i < 2; i++)
#pragma unroll
        for (int j = 0; j < 8; j++)
#pragma unroll
            for (int k = 0; k < 4; k++) acc[i][j][k] = 0.f;

    float4 pa[2][2], pb[4][2];
    const float4 z4 = make_float4(0.f, 0.f, 0.f, 0.f);

    auto loadTile = [&](int t) {
#pragma unroll
        for (int u = 0; u < 2; u++) {
            int gm = bm0 + aM[u];
            int ka = kS + t * 32 + aG[u] * 8;
            if (gm < M) {
                const float* p = A + (size_t)gm * K + ka;
                pa[u][0] = *(const float4*)p; pa[u][1] = *(const float4*)(p + 4);
            } else { pa[u][0] = z4; pa[u][1] = z4; }
        }
#pragma unroll
        for (int u = 0; u < 4; u++) {
            int gn = bn0 + bC[u] * 8;
            int kb = kS + t * 32 + bKr[u];
            if (gn < N) {
                const float* p = B + (size_t)kb * N + gn;
                pb[u][0] = *(const float4*)p; pb[u][1] = *(const float4*)(p + 4);
            } else { pb[u][0] = z4; pb[u][1] = z4; }
        }
    };

    loadTile(0);
    int T = kSplit / 32;
    for (int t = 0; t < T; t++) {
#pragma unroll
        for (int u = 0; u < 2; u++) {
            uint4 hi, lo;
            cvt8(pa[u][0], pa[u][1], hi, lo);
            uint32_t off = aM[u] * 64 + ((uint32_t)(aG[u] ^ ((aM[u] >> 1) & 3)) << 4);
            *(uint4*)(sm + off) = hi;
            *(uint4*)(sm + 4096 + off) = lo;
        }
#pragma unroll
        for (int u = 0; u < 4; u++) {
            uint4 hi, lo;
            cvt8(pb[u][0], pb[u][1], hi, lo);
            uint32_t off = 8192 + bKr[u] * 256 + ((uint32_t)(bC[u] ^ (bKr[u] & 7)) << 4);
            *(uint4*)(sm + off) = hi;
            *(uint4*)(sm + 8192 + off) = lo;
        }
        __syncthreads();

        if (t + 1 < T) loadTile(t + 1);

#pragma unroll
        for (int s = 0; s < 2; s++) {
            uint32_t aH0[4], aL0[4], aH1[4], aL1[4];
            uint32_t ad0 = aRow0 + ((uint32_t)((2 * s + cbitA) ^ swzA0) << 4);
            uint32_t ad1 = aRow1 + ((uint32_t)((2 * s + cbitA) ^ swzA1) << 4);
            ldsm4(aH0, ad0); ldsm4(aL0, ad0 + 4096);
            ldsm4(aH1, ad1); ldsm4(aL1, ad1 + 4096);
            uint32_t bH[4][4], bL[4][4];
#pragma unroll
            for (int g = 0; g < 4; g++) {
                uint32_t bd = bOffG[g] + s * 4096;
                ldsm4t(bH[g], bd);
                ldsm4t(bL[g], bd + 8192);
            }
#pragma unroll
            for (int mf = 0; mf < 2; mf++) {
                const uint32_t* aH = mf ? aH1 : aH0;
                const uint32_t* aL = mf ? aL1 : aL0;
#pragma unroll
                for (int nf = 0; nf < 8; nf++) {
                    int g = nf >> 1;
                    const uint32_t* pbH = &bH[g][(nf & 1) * 2];
                    const uint32_t* pbL = &bL[g][(nf & 1) * 2];
                    mma_bf16(acc[mf][nf], aL, pbH);
                    mma_bf16(acc[mf][nf], aH, pbL);
                    mma_bf16(acc[mf][nf], aH, pbH);
                }
            }
        }
        __syncthreads();
    }

#pragma unroll
    for (int mf = 0; mf < 2; mf++)
#pragma unroll
        for (int nf = 0; nf < 8; nf++)
#pragma unroll
            for (int ci = 0; ci < 4; ci++) {
                int m = bm0 + wm0 + mf * 16 + lq + ((ci >= 2) ? 8 : 0);
                int n = bn0 + wn0 + nf * 8 + lr * 2 + (ci & 1);
                if (m >= M || n >= N) continue;
                C[(size_t)m * N + n] = acc[mf][nf][ci];
            }
}

// ---------------- w1 row permutation ------------------------------------------
__global__ __launch_bounds__(256)
void permute_w1_kernel(const float* __restrict__ w1, float* __restrict__ w1p) {
    int k = blockIdx.x;
    int d = k / 49, bin = k - d * 49;
    int kp = bin * 64 + d;
    w1p[(size_t)kp * 256 + threadIdx.x] = w1[(size_t)k * 256 + threadIdx.x];
}

// ---------------- generic split-K combine: H = epi(sum_z P_z + bias) ----------
template <int EPI, int Z>
__global__ __launch_bounds__(256)
void combine_k(const float* __restrict__ P, const float* __restrict__ bias,
               float* __restrict__ H, int total, int nMask) {
    int i = blockIdx.x * 256 + threadIdx.x;
    if (i < total) {
        float v = bias[i & nMask];
#pragma unroll
        for (int z = 0; z < Z; z++)
            v += P[(size_t)z * total + i];
        if (EPI == 1) v = fmaxf(v, 0.f);
        else if (EPI == 3) v = tanhf(v);
        H[i] = v;
    }
}

// ---------------- build X rows: match_any per-bin dedup + float4 gathers -----
__global__ __launch_bounds__(256)
void build_x_kernel(const float* __restrict__ ref, const float* __restrict__ p1_b) {
    int blk = blockIdx.x;                 // lvl*600 + b*300 + q
    int lvl = blk / BQ;
    int rem = blk - lvl * BQ;
    int b = rem / NQ;
    int q = rem - b * NQ;
    int W = c_dim[lvl];
    int start = c_start[lvl];
    const float* r6 = ref + ((size_t)(b * NQ + q) * LVLS + lvl) * 6;
    float sx, sy, bw, bh;
    box_geom(r6, W, sx, sy, bw, bh);

    __shared__ int   sIdx[196][4];
    __shared__ float sW[196][4];
    __shared__ int   sBI[784];            // per-entry idx  (bin*16 + j)
    __shared__ float sBW[784];            // per-entry merged weight (0 if dup)
    int tid = threadIdx.x;
    int warp = tid >> 5, lane = tid & 31;
    if (tid < 196) {
        int si = tid / 14, sj = tid - si * 14;
        int idx4[4]; float wt4[4];
        sample4(sx, sy, bw, bh, W, si, sj, idx4, wt4);
#pragma unroll
        for (int k = 0; k < 4; k++) { sIdx[tid][k] = idx4[k]; sW[tid][k] = wt4[k]; }
    }
    __syncthreads();

    // parallel per-bin dedup (match_any; key includes bin so bins stay separate)
    for (int g = warp; g < 25; g += 8) {       // 25 groups of 32 cover 784 entries
        int e = g * 32 + lane;
        int bin = e >> 4, j = e & 15;
        int idx = 0; float w = 0.f;
        if (e < 784) {
            int h = bin / 7, w_ = bin - h * 7;
            int s2 = j >> 2, cr = j & 3;
            int s = (2 * h + (s2 >> 1)) * 14 + 2 * w_ + (s2 & 1);
            idx = sIdx[s][cr];
            w = sW[s][cr];
        }
        unsigned key = ((unsigned)bin << 15) | (unsigned)idx;
        unsigned mask = __match_any_sync(0xffffffffu, key);
        int leader = __ffs(mask) - 1;
        float tot = 0.f;
#pragma unroll
        for (int bb = 0; bb < 32; bb++) {
            float wb2 = __shfl_sync(0xffffffffu, w, bb);
            if ((mask >> bb) & 1) tot += wb2;
        }
        if (e < 784) {
            sBW[e] = (lane == leader) ? tot : 0.f;
            sBI[e] = idx;
        }
    }
    __syncthreads();

    int sub = tid >> 4;                    // 0..15 (bin subgroup)
    int d4  = (tid & 15) * 4;              // channel base
    const float* projB = g_proj + ((size_t)b * TOTALPIX + start) * 64 + d4;
    float4 bias4 = *(const float4*)(p1_b + d4);
    float* Xrow = g_X + (size_t)blk * XCOLS;
    for (int bin = sub; bin < 49; bin += 16) {
        int base = bin * 16;
        float4 acc = make_float4(0.f, 0.f, 0.f, 0.f);
#pragma unroll
        for (int e = 0; e < 16; e++) {
            float w = sBW[base + e];
            if (w != 0.f) {
                const float4 v = *(const float4*)(projB + (size_t)sBI[base + e] * 64);
                acc.x += w * v.x; acc.y += w * v.y;
                acc.z += w * v.z; acc.w += w * v.w;
            }
        }
        float4 o;
        o.x = fmaxf(acc.x + bias4.x, 0.f);
        o.y = fmaxf(acc.y + bias4.y, 0.f);
        o.z = fmaxf(acc.z + bias4.z, 0.f);
        o.w = fmaxf(acc.w + bias4.w, 0.f);
        *(float4*)(Xrow + bin * 64 + d4) = o;
    }
}

// ---------------- finalize: dedup + compact gathers + float4 loads -----------
__global__ __launch_bounds__(256)
void finalize_kernel(const float* __restrict__ memory, const float* __restrict__ ref,
                     const float* __restrict__ a2w, const float* __restrict__ a2b,
                     float* __restrict__ out) {
    int bq = blockIdx.x;                   // b*300 + q
    int b = bq / NQ;
    int tid = threadIdx.x;

    __shared__ float qe_s[32][HIDDEN];     // 32 KB
    __shared__ float wArr[2048];           // 8 KB
    __shared__ unsigned short iArr[2048];  // 4 KB
    __shared__ unsigned short cntArr[64];
    __shared__ float logits[32];
    __shared__ float wgt[32];

    for (int e = tid; e < 2048; e += 256) {
        int lvl = e >> 9;
        int head = (e >> 6) & 7;
        int bc = (e >> 4) & 3;
        int sm = (e >> 2) & 3;
        int cr = e & 3;
        int W = c_dim[lvl];
        int start = c_start[lvl];
        const float* r6 = ref + ((size_t)bq * LVLS + lvl) * 6;
        float sx, sy, bw, bh;
        box_geom(r6, W, sx, sy, bw, bh);

        int row = lvl * BQ + bq;
        float gx = g_pts[row * 16 + 2 * head];
        float gy = g_pts[row * 16 + 2 * head + 1];
        float ix = ((gx + 1.f) * 7.f - 1.f) * 0.5f;
        float iy = ((gy + 1.f) * 7.f - 1.f) * 0.5f;
        float bxf = floorf(ix), byf = floorf(iy);
        float lx = ix - bxf, ly = iy - byf;
        int dby = bc >> 1, dbx = bc & 1;
        int bi = (int)byf + dby, bj = (int)bxf + dbx;
        float wb = (dby ? ly : 1.f - ly) * (dbx ? lx : 1.f - lx);
        if (bi < 0 || bi > 6 || bj < 0 || bj > 6) wb = 0.f;
        int si = 2 * bi + (sm >> 1);
        int sj = 2 * bj + (sm & 1);
        int idx4[4]; float wt4[4];
        sample4(sx, sy, bw, bh, W, si, sj, idx4, wt4);
        wArr[e] = wb * wt4[cr];
        iArr[e] = (unsigned short)(b * TOTALPIX + start + idx4[cr]);
    }
    __syncthreads();

    // dedup + compact per 32-entry half of each (lvl,head) group
    {
        int warp = tid >> 5, lane = tid & 31;
        for (int h = warp; h < 64; h += 8) {
            int e = h * 32 + lane;
            unsigned idx = iArr[e];
            float w = wArr[e];
            unsigned mask = __match_any_sync(0xffffffffu, idx);
            int leader = __ffs(mask) - 1;
            float tot = 0.f;
#pragma unroll
            for (int bb = 0; bb < 32; bb++) {
                float wb2 = __shfl_sync(0xffffffffu, w, bb);
                if ((mask >> bb) & 1) tot += wb2;
            }
            float wn = (lane == leader) ? tot : 0.f;
            unsigned bal = __ballot_sync(0xffffffffu, wn != 0.f);
            int pos = __popc(bal & ((1u << lane) - 1));
            if (wn != 0.f) {
                wArr[h * 32 + pos] = wn;
                iArr[h * 32 + pos] = (unsigned short)idx;
            }
            if (lane == 0) cntArr[h] = (unsigned short)__popc(bal);
        }
    }
    __syncthreads();

    const float* gateRow = g_gate + (size_t)bq * (NHEADS * HIDDEN);
    int g64 = tid >> 6;                    // 0..3
    int c4 = (tid & 63) * 4;               // channel base
    for (int lh = g64; lh < 32; lh += 4) {
        float4 acc = make_float4(0.f, 0.f, 0.f, 0.f);
        int eb = lh << 6;
        int n0 = cntArr[2 * lh], n1 = cntArr[2 * lh + 1];
        for (int e = 0; e < n0; e++) {
            float w = wArr[eb + e];
            const float4 v = *(const float4*)(memory + (size_t)iArr[eb + e] * HIDDEN + c4);
            acc.x += w * v.x; acc.y += w * v.y;
            acc.z += w * v.z; acc.w += w * v.w;
        }
        for (int e = 0; e < n1; e++) {
            float w = wArr[eb + 32 + e];
            const float4 v = *(const float4*)(memory + (size_t)iArr[eb + 32 + e] * HIDDEN + c4);
            acc.x += w * v.x; acc.y += w * v.y;
            acc.z += w * v.z; acc.w += w * v.w;
        }
        const float4 gt = *(const float4*)(gateRow + (lh & 7) * HIDDEN + c4);
        qe_s[lh][c4 + 0] = acc.x * gt.x;
        qe_s[lh][c4 + 1] = acc.y * gt.y;
        qe_s[lh][c4 + 2] = acc.z * gt.z;
        qe_s[lh][c4 + 3] = acc.w * gt.w;
    }
    __syncthreads();

    int warp = tid >> 5, lane = tid & 31;
    for (int r = warp; r < 32; r += 8) {
        float s = 0.f;
#pragma unroll
        for (int c2 = lane; c2 < HIDDEN; c2 += 32) s += qe_s[r][c2] * a2w[c2];
#pragma unroll
        for (int o = 16; o; o >>= 1) s += __shfl_xor_sync(0xffffffffu, s, o);
        if (lane == 0) logits[r] = s + a2b[0];
    }
    __syncthreads();

    if (tid < 32) {
        float l = logits[tid];
        float mx = l;
#pragma unroll
        for (int o = 16; o; o >>= 1) mx = fmaxf(mx, __shfl_xor_sync(0xffffffffu, mx, o));
        float ex = expf(l - mx);
        float sum = ex;
#pragma unroll
        for (int o = 16; o; o >>= 1) sum += __shfl_xor_sync(0xffffffffu, sum, o);
        wgt[tid] = ex / sum;
    }
    __syncthreads();

    int c = tid;
    float o = 0.f;
#pragma unroll
    for (int r = 0; r < 32; r++) o += wgt[r] * qe_s[r][c];
    out[(size_t)bq * HIDDEN + c] = o;
}

// -----------------------------------------------------------------------------
static inline int cdiv(int a, int b) { return (a + b - 1) / b; }

extern "C" void kernel_launch(void* const* d_in, const int* in_sizes, int n_in,
                              void* d_out, int out_size) {
    const float* tgt    = (const float*)d_in[0];
    const float* memory = (const float*)d_in[1];
    const float* ref    = (const float*)d_in[2];
    const float* p1_w = (const float*)d_in[4];
    const float* p1_b = (const float*)d_in[5];
    const float* w1   = (const float*)d_in[6];
    const float* b1   = (const float*)d_in[7];
    const float* w2   = (const float*)d_in[8];
    const float* b2   = (const float*)d_in[9];
    const float* w3   = (const float*)d_in[10];
    const float* b3   = (const float*)d_in[11];
    const float* w4   = (const float*)d_in[12];
    const float* b4   = (const float*)d_in[13];
    const float* a1w  = (const float*)d_in[14];
    const float* a1b  = (const float*)d_in[15];
    const float* a2w  = (const float*)d_in[16];
    const float* a2b  = (const float*)d_in[17];
    float* out = (float*)d_out;

    float *gate, *proj, *X, *w1p, *P, *H1, *H2, *H3, *pts;
    cudaGetSymbolAddress((void**)&gate, g_gate);
    cudaGetSymbolAddress((void**)&proj, g_proj);
    cudaGetSymbolAddress((void**)&X,    g_X);
    cudaGetSymbolAddress((void**)&w1p,  g_w1p);
    cudaGetSymbolAddress((void**)&P,    g_P);
    cudaGetSymbolAddress((void**)&H1,   g_H1);
    cudaGetSymbolAddress((void**)&H2,   g_H2);
    cudaGetSymbolAddress((void**)&H3,   g_H3);
    cudaGetSymbolAddress((void**)&pts,  g_pts);

    dim3 t(128);
    // w1 row permutation (independent)
    permute_w1_kernel<<<XCOLS, 256>>>(w1, w1p);
    // gate = sigmoid(tgt @ attn1_w + attn1_b)   (600 x 2048, K=256)
    bf_gemm<2><<<dim3(32, 10, 1), t>>>(tgt, a1w, a1b, gate, BQ, 2048, 256, 256);
    // proj = memory @ p1_w                       (43520 x 64, K=256)
    bf_gemm<0><<<dim3(1, 680, 1), t>>>(memory, p1_w, nullptr, proj, BS * TOTALPIX, 64, 256, 256);
    // X rows via roi_align on projected memory (permuted col layout, deduped)
    build_x_kernel<<<NROWS, 256>>>(ref, p1_b);
    // MLP layer 1: WIDE tiles + split-K=7 (slabs of 448), then combine
    bf_gemm_w<<<dim3(2, 38, KSPLIT1), t>>>(X, w1p, P, NROWS, 256, XCOLS, 448);
    combine_k<1, KSPLIT1><<<cdiv(NROWS * 256, 256), 256>>>(P, b1, H1, NROWS * 256, 255);
    // MLP layer 2 (no split)
    bf_gemm<1><<<dim3(8, 38, 1), t>>>(H1, w2, b2, H2, NROWS, 512, 256, 256);
    // MLP layer 3: split-K=2, combine(relu)
    bf_gemm<0><<<dim3(8, 38, 2), t>>>(H2, w3, nullptr, P, NROWS, 512, 512, 256);
    combine_k<1, 2><<<cdiv(NROWS * 512, 256), 256>>>(P, b3, H3, NROWS * 512, 511);
    // MLP layer 4 (pts): split-K=4, combine(tanh)
    bf_gemm<0><<<dim3(1, 38, 4), t>>>(H3, w4, nullptr, P, NROWS, 16, 512, 128);
    combine_k<3, 4><<<cdiv(NROWS * 16, 256), 256>>>(P, b4, pts, NROWS * 16, 15);
    // grid-sample recompute + gate + softmax combine
    finalize_kernel<<<BQ, 256>>>(memory, ref, a2w, a2b, out);
}

// round 16
// speedup vs baseline: 1.1489x; 1.0886x over previous
#include <cuda_runtime.h>
#include <cuda_bf16.h>
#include <math.h>
#include <stdint.h>

#define HIDDEN   256
#define NQ       300
#define BS       2
#define LVLS     4
#define NHEADS   8
#define TOTALPIX 21760
#define BQ       (BS*NQ)          // 600
#define NROWS    (LVLS*BS*NQ)     // 2400
#define XCOLS    3136
#define KSPLIT1  7                // 3136 = 7*448

// ---------------- scratch (static device globals; no runtime alloc) ----------
__device__ float g_gate[BQ * NHEADS * HIDDEN];   // 600 x 2048
__device__ float g_proj[BS * TOTALPIX * 64];     // projected memory
__device__ float g_X  [NROWS * XCOLS];           // MLP input rows (permuted cols)
__device__ float g_w1p[XCOLS * 256];             // w1 with permuted rows
__device__ float g_P  [KSPLIT1 * NROWS * 256];   // split-K partials (reused)
__device__ float g_H1 [NROWS * 256];
__device__ float g_H2 [NROWS * 512];
__device__ float g_H3 [NROWS * 512];

__device__ __constant__ int c_dim[4]   = {128, 64, 32, 16};
__device__ __constant__ int c_start[4] = {0, 16384, 20480, 21504};

// ---------------- shared geometry helper (roi_align sampling) ----------------
__device__ __forceinline__ void sample4(float sx, float sy, float bw, float bh,
                                        int W, int si, int sj,
                                        int idx[4], float wt[4]) {
    float Wf = (float)W;
    float ty = (float)(si >> 1) + 0.25f + 0.5f * (float)(si & 1);
    float tx = (float)(sj >> 1) + 0.25f + 0.5f * (float)(sj & 1);
    float y = sy + bh * ty;
    float x = sx + bw * tx;
    bool valid = (y >= -1.f) && (y <= Wf) && (x >= -1.f) && (x <= Wf);
    float yc = fminf(fmaxf(y, 0.f), Wf - 1.f);
    float xc = fminf(fmaxf(x, 0.f), Wf - 1.f);
    float y0 = fminf(floorf(yc), Wf - 2.f);
    float x0 = fminf(floorf(xc), Wf - 2.f);
    float ly = yc - y0, lx = xc - x0;
    int yi = (int)y0, xi = (int)x0;
    int p = yi * W + xi;
    float vm = valid ? 0.25f : 0.f;
    float oy = 1.f - ly, ox = 1.f - lx;
    idx[0] = p;         wt[0] = oy * ox * vm;
    idx[1] = p + 1;     wt[1] = oy * lx * vm;
    idx[2] = p + W;     wt[2] = ly * ox * vm;
    idx[3] = p + W + 1; wt[3] = ly * lx * vm;
}

__device__ __forceinline__ void box_geom(const float* __restrict__ r6, int W,
                                         float& sx, float& sy, float& bw, float& bh) {
    float Wf = (float)W;
    float cx = r6[0], cy = r6[1];
    float x1 = fminf(fmaxf(cx - r6[2], 0.f), 1.f) * Wf;
    float y1 = fminf(fmaxf(cy - r6[3], 0.f), 1.f) * Wf;
    float x2 = fminf(fmaxf(cx + r6[4], 0.f), 1.f) * Wf;
    float y2 = fminf(fmaxf(cy + r6[5], 0.f), 1.f) * Wf;
    sx = x1 - 0.5f; sy = y1 - 0.5f;
    bw = (x2 - x1) / 7.f; bh = (y2 - y1) / 7.f;
}

// ================== shared mma building blocks ================================
__device__ __forceinline__ void cvt8(float4 u, float4 v, uint4& hi, uint4& lo) {
    __nv_bfloat162 h0 = __floats2bfloat162_rn(u.x, u.y);
    __nv_bfloat162 h1 = __floats2bfloat162_rn(u.z, u.w);
    __nv_bfloat162 h2 = __floats2bfloat162_rn(v.x, v.y);
    __nv_bfloat162 h3 = __floats2bfloat162_rn(v.z, v.w);
    hi.x = *(uint32_t*)&h0; hi.y = *(uint32_t*)&h1;
    hi.z = *(uint32_t*)&h2; hi.w = *(uint32_t*)&h3;
    __nv_bfloat162 l0 = __floats2bfloat162_rn(u.x - __bfloat162float(h0.x),
                                              u.y - __bfloat162float(h0.y));
    __nv_bfloat162 l1 = __floats2bfloat162_rn(u.z - __bfloat162float(h1.x),
                                              u.w - __bfloat162float(h1.y));
    __nv_bfloat162 l2 = __floats2bfloat162_rn(v.x - __bfloat162float(h2.x),
                                              v.y - __bfloat162float(h2.y));
    __nv_bfloat162 l3 = __floats2bfloat162_rn(v.z - __bfloat162float(h3.x),
                                              v.w - __bfloat162float(h3.y));
    lo.x = *(uint32_t*)&l0; lo.y = *(uint32_t*)&l1;
    lo.z = *(uint32_t*)&l2; lo.w = *(uint32_t*)&l3;
}

__device__ __forceinline__ void ldsm4(uint32_t r[4], uint32_t addr) {
    asm volatile("ldmatrix.sync.aligned.m8n8.x4.shared.b16 {%0,%1,%2,%3}, [%4];"
                 : "=r"(r[0]), "=r"(r[1]), "=r"(r[2]), "=r"(r[3]) : "r"(addr));
}
__device__ __forceinline__ void ldsm4t(uint32_t r[4], uint32_t addr) {
    asm volatile("ldmatrix.sync.aligned.m8n8.x4.trans.shared.b16 {%0,%1,%2,%3}, [%4];"
                 : "=r"(r[0]), "=r"(r[1]), "=r"(r[2]), "=r"(r[3]) : "r"(addr));
}
__device__ __forceinline__ void mma_bf16(float c[4], const uint32_t a[4], const uint32_t* b) {
    asm volatile(
        "mma.sync.aligned.m16n8k16.row.col.f32.bf16.bf16.f32 "
        "{%0,%1,%2,%3},{%4,%5,%6,%7},{%8,%9},{%0,%1,%2,%3};"
        : "+f"(c[0]), "+f"(c[1]), "+f"(c[2]), "+f"(c[3])
        : "r"(a[0]), "r"(a[1]), "r"(a[2]), "r"(a[3]), "r"(b[0]), "r"(b[1]));
}

// ================== narrow GEMM: BM=64 BN=64 (round-4 proven, unchanged) =====
template <int EPI>   // 0 none, 1 relu, 2 sigmoid, 3 tanh
__global__ __launch_bounds__(128, 4)
void bf_gemm(const float* __restrict__ A, const float* __restrict__ B,
             const float* __restrict__ bias, float* __restrict__ C,
             int M, int N, int K, int kSplit) {
    __shared__ __align__(16) unsigned char sm[16384];
    uint32_t sbase = (uint32_t)__cvta_generic_to_shared(sm);

    int bn0 = blockIdx.x * 64, bm0 = blockIdx.y * 64;
    int kS = blockIdx.z * kSplit;
    C += (size_t)blockIdx.z * M * N;

    int tid = threadIdx.x, warp = tid >> 5, lane = tid & 31;
    int wm0 = (warp & 1) * 32, wn0 = (warp >> 1) * 32;
    int lq = lane >> 2, lr = lane & 3;

    int aM[2], aG[2], bK[2], bNg[2];
#pragma unroll
    for (int u = 0; u < 2; u++) {
        int e = tid + 128 * u;
        aM[u] = e >> 2; aG[u] = e & 3;
        bK[u] = e >> 3; bNg[u] = e & 7;
    }

    int matSel = lane >> 3;
    int rowA = (lane & 7) + ((matSel & 1) << 3);
    int cbitA = matSel >> 1;
    int rA0 = wm0 + rowA, rA1 = wm0 + 16 + rowA;
    int swzA0 = (rA0 >> 1) & 3, swzA1 = (rA1 >> 1) & 3;
    uint32_t aRow0 = sbase + rA0 * 64;
    uint32_t aRow1 = sbase + rA1 * 64;

    int kr0 = (lane & 7) + ((matSel & 1) << 3);
    int cb0 = (wn0 >> 3) + (matSel >> 1);
    int cb2 = cb0 + 2;
    uint32_t bOff0 = sbase + 8192 + kr0 * 128 + ((uint32_t)(cb0 ^ (kr0 & 7)) << 4);
    uint32_t bOff2 = sbase + 8192 + kr0 * 128 + ((uint32_t)(cb2 ^ (kr0 & 7)) << 4);

    float acc[2][4][4];
#pragma unroll
    for (int i = 0; i < 2; i++)
#pragma unroll
        for (int j = 0; j < 4; j++)
#pragma unroll
            for (int k = 0; k < 4; k++) acc[i][j][k] = 0.f;

    float4 pa[2][2], pb[2][2];
    const float4 z4 = make_float4(0.f, 0.f, 0.f, 0.f);

    auto loadTile = [&](int t) {
#pragma unroll
        for (int u = 0; u < 2; u++) {
            int gm = bm0 + aM[u];
            int ka = kS + t * 32 + aG[u] * 8;
            if (gm < M) {
                const float* p = A + (size_t)gm * K + ka;
                pa[u][0] = *(const float4*)p; pa[u][1] = *(const float4*)(p + 4);
            } else { pa[u][0] = z4; pa[u][1] = z4; }
            int gn = bn0 + bNg[u] * 8;
            int kb = kS + t * 32 + bK[u];
            if (gn < N) {
                const float* p = B + (size_t)kb * N + gn;
                pb[u][0] = *(const float4*)p; pb[u][1] = *(const float4*)(p + 4);
            } else { pb[u][0] = z4; pb[u][1] = z4; }
        }
    };

    loadTile(0);
    int T = kSplit / 32;
    for (int t = 0; t < T; t++) {
#pragma unroll
        for (int u = 0; u < 2; u++) {
            uint4 hi, lo;
            cvt8(pa[u][0], pa[u][1], hi, lo);
            uint32_t off = aM[u] * 64 + ((uint32_t)(aG[u] ^ ((aM[u] >> 1) & 3)) << 4);
            *(uint4*)(sm + off) = hi;
            *(uint4*)(sm + 4096 + off) = lo;
            cvt8(pb[u][0], pb[u][1], hi, lo);
            off = 8192 + bK[u] * 128 + ((uint32_t)(bNg[u] ^ (bK[u] & 7)) << 4);
            *(uint4*)(sm + off) = hi;
            *(uint4*)(sm + 4096 + off) = lo;
        }
        __syncthreads();

        if (t + 1 < T) loadTile(t + 1);

#pragma unroll
        for (int s = 0; s < 2; s++) {
            uint32_t aH0[4], aL0[4], aH1[4], aL1[4];
            uint32_t ad0 = aRow0 + ((uint32_t)((2 * s + cbitA) ^ swzA0) << 4);
            uint32_t ad1 = aRow1 + ((uint32_t)((2 * s + cbitA) ^ swzA1) << 4);
            ldsm4(aH0, ad0); ldsm4(aL0, ad0 + 4096);
            ldsm4(aH1, ad1); ldsm4(aL1, ad1 + 4096);
            uint32_t bH01[4], bL01[4], bH23[4], bL23[4];
            uint32_t bd0 = bOff0 + s * 2048, bd2 = bOff2 + s * 2048;
            ldsm4t(bH01, bd0); ldsm4t(bL01, bd0 + 4096);
            ldsm4t(bH23, bd2); ldsm4t(bL23, bd2 + 4096);

#pragma unroll
            for (int mf = 0; mf < 2; mf++) {
                const uint32_t* aH = mf ? aH1 : aH0;
                const uint32_t* aL = mf ? aL1 : aL0;
#pragma unroll
                for (int nf = 0; nf < 4; nf++) {
                    const uint32_t* bH = (nf < 2) ? &bH01[(nf & 1) * 2] : &bH23[(nf & 1) * 2];
                    const uint32_t* bL = (nf < 2) ? &bL01[(nf & 1) * 2] : &bL23[(nf & 1) * 2];
                    mma_bf16(acc[mf][nf], aL, bH);
                    mma_bf16(acc[mf][nf], aH, bL);
                    mma_bf16(acc[mf][nf], aH, bH);
                }
            }
        }
        __syncthreads();
    }

#pragma unroll
    for (int mf = 0; mf < 2; mf++)
#pragma unroll
        for (int nf = 0; nf < 4; nf++)
#pragma unroll
            for (int ci = 0; ci < 4; ci++) {
                int m = bm0 + wm0 + mf * 16 + lq + ((ci >= 2) ? 8 : 0);
                int n = bn0 + wn0 + nf * 8 + lr * 2 + (ci & 1);
                if (m >= M || n >= N) continue;
                float v = acc[mf][nf][ci] + (bias ? bias[n] : 0.f);
                if (EPI == 1) v = fmaxf(v, 0.f);
                else if (EPI == 2) v = 1.f / (1.f + expf(-v));
                else if (EPI == 3) v = tanhf(v);
                C[(size_t)m * N + n] = v;
            }
}

// ================== wide GEMM: BM=64 BN=128, warp tile 32x64 =================
__global__ __launch_bounds__(128, 2)
void bf_gemm_w(const float* __restrict__ A, const float* __restrict__ B,
               float* __restrict__ C, int M, int N, int K, int kSplit) {
    __shared__ __align__(16) unsigned char sm[24576];
    uint32_t sbase = (uint32_t)__cvta_generic_to_shared(sm);

    int bn0 = blockIdx.x * 128, bm0 = blockIdx.y * 64;
    int kS = blockIdx.z * kSplit;
    C += (size_t)blockIdx.z * M * N;

    int tid = threadIdx.x, warp = tid >> 5, lane = tid & 31;
    int wm0 = (warp & 1) * 32, wn0 = (warp >> 1) * 64;
    int lq = lane >> 2, lr = lane & 3;

    int aM[2], aG[2];
#pragma unroll
    for (int u = 0; u < 2; u++) {
        int e = tid + 128 * u;
        aM[u] = e >> 2; aG[u] = e & 3;
    }
    int bKr[4], bC[4];
#pragma unroll
    for (int u = 0; u < 4; u++) {
        int e = tid + 128 * u;
        bKr[u] = e >> 4; bC[u] = e & 15;
    }

    int matSel = lane >> 3;
    int rowA = (lane & 7) + ((matSel & 1) << 3);
    int cbitA = matSel >> 1;
    int rA0 = wm0 + rowA, rA1 = wm0 + 16 + rowA;
    int swzA0 = (rA0 >> 1) & 3, swzA1 = (rA1 >> 1) & 3;
    uint32_t aRow0 = sbase + rA0 * 64;
    uint32_t aRow1 = sbase + rA1 * 64;

    int kr0 = (lane & 7) + ((matSel & 1) << 3);
    int msHalf = matSel >> 1;
    uint32_t bOffG[4];
#pragma unroll
    for (int g = 0; g < 4; g++) {
        int cb = (wn0 >> 3) + 2 * g + msHalf;
        bOffG[g] = sbase + 8192 + kr0 * 256 + ((uint32_t)(cb ^ (kr0 & 7)) << 4);
    }

    float acc[2][8][4];
#pragma unroll
    for (int i = 0; i < 2; i++)
#pragma unroll
        for (int j = 0; j < 8; j++)
#pragma unroll
            for (int k = 0; k < 4; k++) acc[i][j][k] = 0.f;

    float4 pa[2][2], pb[4][2];
    const float4 z4 = make_float4(0.f, 0.f, 0.f, 0.f);

    auto loadTile = [&](int t) {
#pragma unroll
        for (int u = 0; u < 2; u++) {
            int gm = bm0 + aM[u];
            int ka = kS + t * 32 + aG[u] * 8;
            if (gm < M) {
                const float* p = A + (size_t)gm * K + ka;
                pa[u][0] = *(const float4*)p; pa[u][1] = *(const float4*)(p + 4);
            } else { pa[u][0] = z4; pa[u][1] = z4; }
        }
#pragma unroll
        for (int u = 0; u < 4; u++) {
            int gn = bn0 + bC[u] * 8;
            int kb = kS + t * 32 + bKr[u];
            if (gn < N) {
                const float* p = B + (size_t)kb * N + gn;
                pb[u][0] = *(const float4*)p; pb[u][1] = *(const float4*)(p + 4);
            } else { pb[u][0] = z4; pb[u][1] = z4; }
        }
    };

    loadTile(0);
    int T = kSplit / 32;
    for (int t = 0; t < T; t++) {
#pragma unroll
        for (int u = 0; u < 2; u++) {
            uint4 hi, lo;
            cvt8(pa[u][0], pa[u][1], hi, lo);
            uint32_t off = aM[u] * 64 + ((uint32_t)(aG[u] ^ ((aM[u] >> 1) & 3)) << 4);
            *(uint4*)(sm + off) = hi;
            *(uint4*)(sm + 4096 + off) = lo;
        }
#pragma unroll
        for (int u = 0; u < 4; u++) {
            uint4 hi, lo;
            cvt8(pb[u][0], pb[u][1], hi, lo);
            uint32_t off = 8192 + bKr[u] * 256 + ((uint32_t)(bC[u] ^ (bKr[u] & 7)) << 4);
            *(uint4*)(sm + off) = hi;
            *(uint4*)(sm + 8192 + off) = lo;
        }
        __syncthreads();

        if (t + 1 < T) loadTile(t + 1);

#pragma unroll
        for (int s = 0; s < 2; s++) {
            uint32_t aH0[4], aL0[4], aH1[4], aL1[4];
            uint32_t ad0 = aRow0 + ((uint32_t)((2 * s + cbitA) ^ swzA0) << 4);
            uint32_t ad1 = aRow1 + ((uint32_t)((2 * s + cbitA) ^ swzA1) << 4);
            ldsm4(aH0, ad0); ldsm4(aL0, ad0 + 4096);
            ldsm4(aH1, ad1); ldsm4(aL1, ad1 + 4096);
            uint32_t bH[4][4], bL[4][4];
#pragma unroll
            for (int g = 0; g < 4; g++) {
                uint32_t bd = bOffG[g] + s * 4096;
                ldsm4t(bH[g], bd);
                ldsm4t(bL[g], bd + 8192);
            }
#pragma unroll
            for (int mf = 0; mf < 2; mf++) {
                const uint32_t* aH = mf ? aH1 : aH0;
                const uint32_t* aL = mf ? aL1 : aL0;
#pragma unroll
                for (int nf = 0; nf < 8; nf++) {
                    int g = nf >> 1;
                    const uint32_t* pbH = &bH[g][(nf & 1) * 2];
                    const uint32_t* pbL = &bL[g][(nf & 1) * 2];
                    mma_bf16(acc[mf][nf], aL, pbH);
                    mma_bf16(acc[mf][nf], aH, pbL);
                    mma_bf16(acc[mf][nf], aH, pbH);
                }
            }
        }
        __syncthreads();
    }

#pragma unroll
    for (int mf = 0; mf < 2; mf++)
#pragma unroll
        for (int nf = 0; nf < 8; nf++)
#pragma unroll
            for (int ci = 0; ci < 4; ci++) {
                int m = bm0 + wm0 + mf * 16 + lq + ((ci >= 2) ? 8 : 0);
                int n = bn0 + wn0 + nf * 8 + lr * 2 + (ci & 1);
                if (m >= M || n >= N) continue;
                C[(size_t)m * N + n] = acc[mf][nf][ci];
            }
}

// ---------------- w1 row permutation ------------------------------------------
__global__ __launch_bounds__(256)
void permute_w1_kernel(const float* __restrict__ w1, float* __restrict__ w1p) {
    int k = blockIdx.x;
    int d = k / 49, bin = k - d * 49;
    int kp = bin * 64 + d;
    w1p[(size_t)kp * 256 + threadIdx.x] = w1[(size_t)k * 256 + threadIdx.x];
}

// ---------------- generic split-K combine: H = epi(sum_z P_z + bias) ----------
template <int EPI, int Z>
__global__ __launch_bounds__(256)
void combine_k(const float* __restrict__ P, const float* __restrict__ bias,
               float* __restrict__ H, int total, int nMask) {
    int i = blockIdx.x * 256 + threadIdx.x;
    if (i < total) {
        float v = bias[i & nMask];
#pragma unroll
        for (int z = 0; z < Z; z++)
            v += P[(size_t)z * total + i];
        if (EPI == 1) v = fmaxf(v, 0.f);
        else if (EPI == 3) v = tanhf(v);
        H[i] = v;
    }
}

// ---------------- build X rows (permuted cols), dual-acc float4 gathers ------
__global__ __launch_bounds__(256)
void build_x_kernel(const float* __restrict__ ref, const float* __restrict__ p1_b) {
    int blk = blockIdx.x;                 // lvl*600 + b*300 + q
    int lvl = blk / BQ;
    int rem = blk - lvl * BQ;
    int b = rem / NQ;
    int q = rem - b * NQ;
    int W = c_dim[lvl];
    int start = c_start[lvl];
    const float* r6 = ref + ((size_t)(b * NQ + q) * LVLS + lvl) * 6;
    float sx, sy, bw, bh;
    box_geom(r6, W, sx, sy, bw, bh);

    __shared__ float2 sWI[196][4];        // {weight, idx-as-int bits}
    int tid = threadIdx.x;
    if (tid < 196) {
        int si = tid / 14, sj = tid - si * 14;
        int idx4[4]; float wt4[4];
        sample4(sx, sy, bw, bh, W, si, sj, idx4, wt4);
#pragma unroll
        for (int k = 0; k < 4; k++)
            sWI[tid][k] = make_float2(wt4[k], __int_as_float(idx4[k]));
    }
    __syncthreads();

    int sub = tid >> 4;                    // 0..15 (bin subgroup)
    int d4  = (tid & 15) * 4;              // channel base
    const float* projB = g_proj + ((size_t)b * TOTALPIX + start) * 64 + d4;
    float4 bias4 = *(const float4*)(p1_b + d4);
    float* Xrow = g_X + (size_t)blk * XCOLS;
    for (int bin = sub; bin < 49; bin += 16) {
        int h = bin / 7, w_ = bin - h * 7;
        float4 acc0 = make_float4(0.f, 0.f, 0.f, 0.f);
        float4 acc1 = make_float4(0.f, 0.f, 0.f, 0.f);
#pragma unroll
        for (int s2 = 0; s2 < 4; s2++) {
            int s = (2 * h + (s2 >> 1)) * 14 + 2 * w_ + (s2 & 1);
#pragma unroll
            for (int cr = 0; cr < 4; cr++) {
                float2 wi = sWI[s][cr];
                float w = wi.x;
                int idx = __float_as_int(wi.y);
                const float4 v = *(const float4*)(projB + (size_t)idx * 64);
                if (cr & 1) {
                    acc1.x += w * v.x; acc1.y += w * v.y;
                    acc1.z += w * v.z; acc1.w += w * v.w;
                } else {
                    acc0.x += w * v.x; acc0.y += w * v.y;
                    acc0.z += w * v.z; acc0.w += w * v.w;
                }
            }
        }
        float4 o;
        o.x = fmaxf(acc0.x + acc1.x + bias4.x, 0.f);
        o.y = fmaxf(acc0.y + acc1.y + bias4.y, 0.f);
        o.z = fmaxf(acc0.z + acc1.z + bias4.z, 0.f);
        o.w = fmaxf(acc0.w + acc1.w + bias4.w, 0.f);
        *(float4*)(Xrow + bin * 64 + d4) = o;
    }
}

// ---------------- finalize: inline pts combine + dedup/compact gathers -------
__global__ __launch_bounds__(256)
void finalize_kernel(const float* __restrict__ memory, const float* __restrict__ ref,
                     const float* __restrict__ P4, const float* __restrict__ b4,
                     const float* __restrict__ a2w, const float* __restrict__ a2b,
                     float* __restrict__ out) {
    int bq = blockIdx.x;                   // b*300 + q
    int b = bq / NQ;
    int tid = threadIdx.x;

    __shared__ float qe_s[32][HIDDEN];     // 32 KB
    __shared__ float wArr[2048];           // 8 KB
    __shared__ unsigned short iArr[2048];  // 4 KB
    __shared__ unsigned short cntArr[64];
    __shared__ float sPts[64];             // (lvl,head) x {gx,gy}
    __shared__ float logits[32];
    __shared__ float wgt[32];

    // inline pts split-K combine: pts = tanh(b4 + sum_z P_z), rows lvl*BQ+bq
    if (tid < 64) {
        int lvl = tid >> 4;                // 0..3
        int col = tid & 15;                // 0..15 = 2*head + coord
        int row = lvl * BQ + bq;
        float v = b4[col];
#pragma unroll
        for (int z = 0; z < 4; z++)
            v += P4[(size_t)z * NROWS * 16 + (size_t)row * 16 + col];
        sPts[tid] = tanhf(v);
    }
    __syncthreads();

    for (int e = tid; e < 2048; e += 256) {
        int lvl = e >> 9;
        int head = (e >> 6) & 7;
        int bc = (e >> 4) & 3;
        int sm = (e >> 2) & 3;
        int cr = e & 3;
        int W = c_dim[lvl];
        int start = c_start[lvl];
        const float* r6 = ref + ((size_t)bq * LVLS + lvl) * 6;
        float sx, sy, bw, bh;
        box_geom(r6, W, sx, sy, bw, bh);

        float gx = sPts[lvl * 16 + 2 * head];
        float gy = sPts[lvl * 16 + 2 * head + 1];
        float ix = ((gx + 1.f) * 7.f - 1.f) * 0.5f;
        float iy = ((gy + 1.f) * 7.f - 1.f) * 0.5f;
        float bxf = floorf(ix), byf = floorf(iy);
        float lx = ix - bxf, ly = iy - byf;
        int dby = bc >> 1, dbx = bc & 1;
        int bi = (int)byf + dby, bj = (int)bxf + dbx;
        float wb = (dby ? ly : 1.f - ly) * (dbx ? lx : 1.f - lx);
        if (bi < 0 || bi > 6 || bj < 0 || bj > 6) wb = 0.f;
        int si = 2 * bi + (sm >> 1);
        int sj = 2 * bj + (sm & 1);
        int idx4[4]; float wt4[4];
        sample4(sx, sy, bw, bh, W, si, sj, idx4, wt4);
        wArr[e] = wb * wt4[cr];
        iArr[e] = (unsigned short)(b * TOTALPIX + start + idx4[cr]);
    }
    __syncthreads();

    // dedup + compact per 32-entry half of each (lvl,head) group
    {
        int warp = tid >> 5, lane = tid & 31;
        for (int h = warp; h < 64; h += 8) {
            int e = h * 32 + lane;
            unsigned idx = iArr[e];
            float w = wArr[e];
            unsigned mask = __match_any_sync(0xffffffffu, idx);
            int leader = __ffs(mask) - 1;
            float tot = 0.f;
#pragma unroll
            for (int bb = 0; bb < 32; bb++) {
                float wb2 = __shfl_sync(0xffffffffu, w, bb);
                if ((mask >> bb) & 1) tot += wb2;
            }
            float wn = (lane == leader) ? tot : 0.f;
            unsigned bal = __ballot_sync(0xffffffffu, wn != 0.f);
            int pos = __popc(bal & ((1u << lane) - 1));
            if (wn != 0.f) {
                wArr[h * 32 + pos] = wn;
                iArr[h * 32 + pos] = (unsigned short)idx;
            }
            if (lane == 0) cntArr[h] = (unsigned short)__popc(bal);
        }
    }
    __syncthreads();

    const float* gateRow = g_gate + (size_t)bq * (NHEADS * HIDDEN);
    int g64 = tid >> 6;                    // 0..3
    int c4 = (tid & 63) * 4;               // channel base
    for (int lh = g64; lh < 32; lh += 4) {
        float4 acc = make_float4(0.f, 0.f, 0.f, 0.f);
        int eb = lh << 6;
        int n0 = cntArr[2 * lh], n1 = cntArr[2 * lh + 1];
        for (int e = 0; e < n0; e++) {
            float w = wArr[eb + e];
            const float4 v = *(const float4*)(memory + (size_t)iArr[eb + e] * HIDDEN + c4);
            acc.x += w * v.x; acc.y += w * v.y;
            acc.z += w * v.z; acc.w += w * v.w;
        }
        for (int e = 0; e < n1; e++) {
            float w = wArr[eb + 32 + e];
            const float4 v = *(const float4*)(memory + (size_t)iArr[eb + 32 + e] * HIDDEN + c4);
            acc.x += w * v.x; acc.y += w * v.y;
            acc.z += w * v.z; acc.w += w * v.w;
        }
        const float4 gt = *(const float4*)(gateRow + (lh & 7) * HIDDEN + c4);
        qe_s[lh][c4 + 0] = acc.x * gt.x;
        qe_s[lh][c4 + 1] = acc.y * gt.y;
        qe_s[lh][c4 + 2] = acc.z * gt.z;
        qe_s[lh][c4 + 3] = acc.w * gt.w;
    }
    __syncthreads();

    int warp = tid >> 5, lane = tid & 31;
    for (int r = warp; r < 32; r += 8) {
        float s = 0.f;
#pragma unroll
        for (int c2 = lane; c2 < HIDDEN; c2 += 32) s += qe_s[r][c2] * a2w[c2];
#pragma unroll
        for (int o = 16; o; o >>= 1) s += __shfl_xor_sync(0xffffffffu, s, o);
        if (lane == 0) logits[r] = s + a2b[0];
    }
    __syncthreads();

    if (tid < 32) {
        float l = logits[tid];
        float mx = l;
#pragma unroll
        for (int o = 16; o; o >>= 1) mx = fmaxf(mx, __shfl_xor_sync(0xffffffffu, mx, o));
        float ex = expf(l - mx);
        float sum = ex;
#pragma unroll
        for (int o = 16; o; o >>= 1) sum += __shfl_xor_sync(0xffffffffu, sum, o);
        wgt[tid] = ex / sum;
    }
    __syncthreads();

    int c = tid;
    float o = 0.f;
#pragma unroll
    for (int r = 0; r < 32; r++) o += wgt[r] * qe_s[r][c];
    out[(size_t)bq * HIDDEN + c] = o;
}

// -----------------------------------------------------------------------------
static inline int cdiv(int a, int b) { return (a + b - 1) / b; }

extern "C" void kernel_launch(void* const* d_in, const int* in_sizes, int n_in,
                              void* d_out, int out_size) {
    const float* tgt    = (const float*)d_in[0];
    const float* memory = (const float*)d_in[1];
    const float* ref    = (const float*)d_in[2];
    const float* p1_w = (const float*)d_in[4];
    const float* p1_b = (const float*)d_in[5];
    const float* w1   = (const float*)d_in[6];
    const float* b1   = (const float*)d_in[7];
    const float* w2   = (const float*)d_in[8];
    const float* b2   = (const float*)d_in[9];
    const float* w3   = (const float*)d_in[10];
    const float* b3   = (const float*)d_in[11];
    const float* w4   = (const float*)d_in[12];
    const float* b4   = (const float*)d_in[13];
    const float* a1w  = (const float*)d_in[14];
    const float* a1b  = (const float*)d_in[15];
    const float* a2w  = (const float*)d_in[16];
    const float* a2b  = (const float*)d_in[17];
    float* out = (float*)d_out;

    float *gate, *proj, *X, *w1p, *P, *H1, *H2, *H3;
    cudaGetSymbolAddress((void**)&gate, g_gate);
    cudaGetSymbolAddress((void**)&proj, g_proj);
    cudaGetSymbolAddress((void**)&X,    g_X);
    cudaGetSymbolAddress((void**)&w1p,  g_w1p);
    cudaGetSymbolAddress((void**)&P,    g_P);
    cudaGetSymbolAddress((void**)&H1,   g_H1);
    cudaGetSymbolAddress((void**)&H2,   g_H2);
    cudaGetSymbolAddress((void**)&H3,   g_H3);

    dim3 t(128);
    // w1 row permutation (independent)
    permute_w1_kernel<<<XCOLS, 256>>>(w1, w1p);
    // gate = sigmoid(tgt @ attn1_w + attn1_b)   (600 x 2048, K=256)
    bf_gemm<2><<<dim3(32, 10, 1), t>>>(tgt, a1w, a1b, gate, BQ, 2048, 256, 256);
    // proj = memory @ p1_w                       (43520 x 64, K=256)
    bf_gemm<0><<<dim3(1, 680, 1), t>>>(memory, p1_w, nullptr, proj, BS * TOTALPIX, 64, 256, 256);
    // X rows via roi_align on projected memory (permuted col layout)
    build_x_kernel<<<NROWS, 256>>>(ref, p1_b);
    // MLP layer 1: WIDE tiles + split-K=7 (slabs of 448), then combine
    bf_gemm_w<<<dim3(2, 38, KSPLIT1), t>>>(X, w1p, P, NROWS, 256, XCOLS, 448);
    combine_k<1, KSPLIT1><<<cdiv(NROWS * 256, 256), 256>>>(P, b1, H1, NROWS * 256, 255);
    // MLP layer 2 (no split)
    bf_gemm<1><<<dim3(8, 38, 1), t>>>(H1, w2, b2, H2, NROWS, 512, 256, 256);
    // MLP layer 3: split-K=2, combine(relu)
    bf_gemm<0><<<dim3(8, 38, 2), t>>>(H2, w3, nullptr, P, NROWS, 512, 512, 256);
    combine_k<1, 2><<<cdiv(NROWS * 512, 256), 256>>>(P, b3, H3, NROWS * 512, 511);
    // MLP layer 4 (pts): split-K=4 partials in P; combined inside finalize
    bf_gemm<0><<<dim3(1, 38, 4), t>>>(H3, w4, nullptr, P, NROWS, 16, 512, 128);
    // grid-sample recompute + inline pts combine + gate + softmax combine
    finalize_kernel<<<BQ, 256>>>(memory, ref, P, b4, a2w, a2b, out);
}

// round 17
// speedup vs baseline: 1.1597x; 1.0094x over previous
#include <cuda_runtime.h>
#include <cuda_bf16.h>
#include <math.h>
#include <stdint.h>

#define HIDDEN   256
#define NQ       300
#define BS       2
#define LVLS     4
#define NHEADS   8
#define TOTALPIX 21760
#define BQ       (BS*NQ)          // 600
#define NROWS    (LVLS*BS*NQ)     // 2400
#define XCOLS    3136
#define KSPLIT1  7                // 3136 = 7*448

// ---------------- scratch (static device globals; no runtime alloc) ----------
__device__ float g_gate[BQ * NHEADS * HIDDEN];   // 600 x 2048
__device__ float g_proj[BS * TOTALPIX * 64];     // projected memory
__device__ float g_X  [NROWS * XCOLS];           // MLP input rows (permuted cols)
__device__ float g_w1p[XCOLS * 256];             // w1 with permuted rows
__device__ float g_P  [KSPLIT1 * NROWS * 256];   // split-K partials (reused)
__device__ float g_H1 [NROWS * 256];             // H1; later pts partials
__device__ float g_H2 [NROWS * 512];

__device__ __constant__ int c_dim[4]   = {128, 64, 32, 16};
__device__ __constant__ int c_start[4] = {0, 16384, 20480, 21504};

// ---------------- shared geometry helper (roi_align sampling) ----------------
__device__ __forceinline__ void sample4(float sx, float sy, float bw, float bh,
                                        int W, int si, int sj,
                                        int idx[4], float wt[4]) {
    float Wf = (float)W;
    float ty = (float)(si >> 1) + 0.25f + 0.5f * (float)(si & 1);
    float tx = (float)(sj >> 1) + 0.25f + 0.5f * (float)(sj & 1);
    float y = sy + bh * ty;
    float x = sx + bw * tx;
    bool valid = (y >= -1.f) && (y <= Wf) && (x >= -1.f) && (x <= Wf);
    float yc = fminf(fmaxf(y, 0.f), Wf - 1.f);
    float xc = fminf(fmaxf(x, 0.f), Wf - 1.f);
    float y0 = fminf(floorf(yc), Wf - 2.f);
    float x0 = fminf(floorf(xc), Wf - 2.f);
    float ly = yc - y0, lx = xc - x0;
    int yi = (int)y0, xi = (int)x0;
    int p = yi * W + xi;
    float vm = valid ? 0.25f : 0.f;
    float oy = 1.f - ly, ox = 1.f - lx;
    idx[0] = p;         wt[0] = oy * ox * vm;
    idx[1] = p + 1;     wt[1] = oy * lx * vm;
    idx[2] = p + W;     wt[2] = ly * ox * vm;
    idx[3] = p + W + 1; wt[3] = ly * lx * vm;
}

__device__ __forceinline__ void box_geom(const float* __restrict__ r6, int W,
                                         float& sx, float& sy, float& bw, float& bh) {
    float Wf = (float)W;
    float cx = r6[0], cy = r6[1];
    float x1 = fminf(fmaxf(cx - r6[2], 0.f), 1.f) * Wf;
    float y1 = fminf(fmaxf(cy - r6[3], 0.f), 1.f) * Wf;
    float x2 = fminf(fmaxf(cx + r6[4], 0.f), 1.f) * Wf;
    float y2 = fminf(fmaxf(cy + r6[5], 0.f), 1.f) * Wf;
    sx = x1 - 0.5f; sy = y1 - 0.5f;
    bw = (x2 - x1) / 7.f; bh = (y2 - y1) / 7.f;
}

// ================== shared mma building blocks ================================
__device__ __forceinline__ void cvt8(float4 u, float4 v, uint4& hi, uint4& lo) {
    __nv_bfloat162 h0 = __floats2bfloat162_rn(u.x, u.y);
    __nv_bfloat162 h1 = __floats2bfloat162_rn(u.z, u.w);
    __nv_bfloat162 h2 = __floats2bfloat162_rn(v.x, v.y);
    __nv_bfloat162 h3 = __floats2bfloat162_rn(v.z, v.w);
    hi.x = *(uint32_t*)&h0; hi.y = *(uint32_t*)&h1;
    hi.z = *(uint32_t*)&h2; hi.w = *(uint32_t*)&h3;
    __nv_bfloat162 l0 = __floats2bfloat162_rn(u.x - __bfloat162float(h0.x),
                                              u.y - __bfloat162float(h0.y));
    __nv_bfloat162 l1 = __floats2bfloat162_rn(u.z - __bfloat162float(h1.x),
                                              u.w - __bfloat162float(h1.y));
    __nv_bfloat162 l2 = __floats2bfloat162_rn(v.x - __bfloat162float(h2.x),
                                              v.y - __bfloat162float(h2.y));
    __nv_bfloat162 l3 = __floats2bfloat162_rn(v.z - __bfloat162float(h3.x),
                                              v.w - __bfloat162float(h3.y));
    lo.x = *(uint32_t*)&l0; lo.y = *(uint32_t*)&l1;
    lo.z = *(uint32_t*)&l2; lo.w = *(uint32_t*)&l3;
}

__device__ __forceinline__ void ldsm4(uint32_t r[4], uint32_t addr) {
    asm volatile("ldmatrix.sync.aligned.m8n8.x4.shared.b16 {%0,%1,%2,%3}, [%4];"
                 : "=r"(r[0]), "=r"(r[1]), "=r"(r[2]), "=r"(r[3]) : "r"(addr));
}
__device__ __forceinline__ void ldsm4t(uint32_t r[4], uint32_t addr) {
    asm volatile("ldmatrix.sync.aligned.m8n8.x4.trans.shared.b16 {%0,%1,%2,%3}, [%4];"
                 : "=r"(r[0]), "=r"(r[1]), "=r"(r[2]), "=r"(r[3]) : "r"(addr));
}
__device__ __forceinline__ void mma_bf16(float c[4], const uint32_t a[4], const uint32_t* b) {
    asm volatile(
        "mma.sync.aligned.m16n8k16.row.col.f32.bf16.bf16.f32 "
        "{%0,%1,%2,%3},{%4,%5,%6,%7},{%8,%9},{%0,%1,%2,%3};"
        : "+f"(c[0]), "+f"(c[1]), "+f"(c[2]), "+f"(c[3])
        : "r"(a[0]), "r"(a[1]), "r"(a[2]), "r"(a[3]), "r"(b[0]), "r"(b[1]));
}

// ================== narrow GEMM: BM=64 BN=64 ================================
// AFUSE=1: A element = relu(abias[k] + A[m,k] + A2[m,k])  (fused combine)
template <int EPI, int AFUSE>   // EPI: 0 none, 1 relu, 2 sigmoid, 3 tanh
__global__ __launch_bounds__(128, 4)
void bf_gemm(const float* __restrict__ A, const float* __restrict__ A2,
             const float* __restrict__ abias,
             const float* __restrict__ B,
             const float* __restrict__ bias, float* __restrict__ C,
             int M, int N, int K, int kSplit) {
    __shared__ __align__(16) unsigned char sm[16384];
    uint32_t sbase = (uint32_t)__cvta_generic_to_shared(sm);

    int bn0 = blockIdx.x * 64, bm0 = blockIdx.y * 64;
    int kS = blockIdx.z * kSplit;
    C += (size_t)blockIdx.z * M * N;

    int tid = threadIdx.x, warp = tid >> 5, lane = tid & 31;
    int wm0 = (warp & 1) * 32, wn0 = (warp >> 1) * 32;
    int lq = lane >> 2, lr = lane & 3;

    int aM[2], aG[2], bK[2], bNg[2];
#pragma unroll
    for (int u = 0; u < 2; u++) {
        int e = tid + 128 * u;
        aM[u] = e >> 2; aG[u] = e & 3;
        bK[u] = e >> 3; bNg[u] = e & 7;
    }

    int matSel = lane >> 3;
    int rowA = (lane & 7) + ((matSel & 1) << 3);
    int cbitA = matSel >> 1;
    int rA0 = wm0 + rowA, rA1 = wm0 + 16 + rowA;
    int swzA0 = (rA0 >> 1) & 3, swzA1 = (rA1 >> 1) & 3;
    uint32_t aRow0 = sbase + rA0 * 64;
    uint32_t aRow1 = sbase + rA1 * 64;

    int kr0 = (lane & 7) + ((matSel & 1) << 3);
    int cb0 = (wn0 >> 3) + (matSel >> 1);
    int cb2 = cb0 + 2;
    uint32_t bOff0 = sbase + 8192 + kr0 * 128 + ((uint32_t)(cb0 ^ (kr0 & 7)) << 4);
    uint32_t bOff2 = sbase + 8192 + kr0 * 128 + ((uint32_t)(cb2 ^ (kr0 & 7)) << 4);

    float acc[2][4][4];
#pragma unroll
    for (int i = 0; i < 2; i++)
#pragma unroll
        for (int j = 0; j < 4; j++)
#pragma unroll
            for (int k = 0; k < 4; k++) acc[i][j][k] = 0.f;

    float4 pa[2][2], pb[2][2];
    const float4 z4 = make_float4(0.f, 0.f, 0.f, 0.f);

    auto loadTile = [&](int t) {
#pragma unroll
        for (int u = 0; u < 2; u++) {
            int gm = bm0 + aM[u];
            int ka = kS + t * 32 + aG[u] * 8;
            if (gm < M) {
                const float* p = A + (size_t)gm * K + ka;
                float4 x0 = *(const float4*)p, x1 = *(const float4*)(p + 4);
                if (AFUSE) {
                    const float* p2 = A2 + (size_t)gm * K + ka;
                    float4 y0 = *(const float4*)p2, y1 = *(const float4*)(p2 + 4);
                    float4 bz0 = *(const float4*)(abias + ka);
                    float4 bz1 = *(const float4*)(abias + ka + 4);
                    x0.x = fmaxf(bz0.x + x0.x + y0.x, 0.f);
                    x0.y = fmaxf(bz0.y + x0.y + y0.y, 0.f);
                    x0.z = fmaxf(bz0.z + x0.z + y0.z, 0.f);
                    x0.w = fmaxf(bz0.w + x0.w + y0.w, 0.f);
                    x1.x = fmaxf(bz1.x + x1.x + y1.x, 0.f);
                    x1.y = fmaxf(bz1.y + x1.y + y1.y, 0.f);
                    x1.z = fmaxf(bz1.z + x1.z + y1.z, 0.f);
                    x1.w = fmaxf(bz1.w + x1.w + y1.w, 0.f);
                }
                pa[u][0] = x0; pa[u][1] = x1;
            } else { pa[u][0] = z4; pa[u][1] = z4; }
            int gn = bn0 + bNg[u] * 8;
            int kb = kS + t * 32 + bK[u];
            if (gn < N) {
                const float* p = B + (size_t)kb * N + gn;
                pb[u][0] = *(const float4*)p; pb[u][1] = *(const float4*)(p + 4);
            } else { pb[u][0] = z4; pb[u][1] = z4; }
        }
    };

    loadTile(0);
    int T = kSplit / 32;
    for (int t = 0; t < T; t++) {
#pragma unroll
        for (int u = 0; u < 2; u++) {
            uint4 hi, lo;
            cvt8(pa[u][0], pa[u][1], hi, lo);
            uint32_t off = aM[u] * 64 + ((uint32_t)(aG[u] ^ ((aM[u] >> 1) & 3)) << 4);
            *(uint4*)(sm + off) = hi;
            *(uint4*)(sm + 4096 + off) = lo;
            cvt8(pb[u][0], pb[u][1], hi, lo);
            off = 8192 + bK[u] * 128 + ((uint32_t)(bNg[u] ^ (bK[u] & 7)) << 4);
            *(uint4*)(sm + off) = hi;
            *(uint4*)(sm + 4096 + off) = lo;
        }
        __syncthreads();

        if (t + 1 < T) loadTile(t + 1);

#pragma unroll
        for (int s = 0; s < 2; s++) {
            uint32_t aH0[4], aL0[4], aH1[4], aL1[4];
            uint32_t ad0 = aRow0 + ((uint32_t)((2 * s + cbitA) ^ swzA0) << 4);
            uint32_t ad1 = aRow1 + ((uint32_t)((2 * s + cbitA) ^ swzA1) << 4);
            ldsm4(aH0, ad0); ldsm4(aL0, ad0 + 4096);
            ldsm4(aH1, ad1); ldsm4(aL1, ad1 + 4096);
            uint32_t bH01[4], bL01[4], bH23[4], bL23[4];
            uint32_t bd0 = bOff0 + s * 2048, bd2 = bOff2 + s * 2048;
            ldsm4t(bH01, bd0); ldsm4t(bL01, bd0 + 4096);
            ldsm4t(bH23, bd2); ldsm4t(bL23, bd2 + 4096);

#pragma unroll
            for (int mf = 0; mf < 2; mf++) {
                const uint32_t* aH = mf ? aH1 : aH0;
                const uint32_t* aL = mf ? aL1 : aL0;
#pragma unroll
                for (int nf = 0; nf < 4; nf++) {
                    const uint32_t* bH = (nf < 2) ? &bH01[(nf & 1) * 2] : &bH23[(nf & 1) * 2];
                    const uint32_t* bL = (nf < 2) ? &bL01[(nf & 1) * 2] : &bL23[(nf & 1) * 2];
                    mma_bf16(acc[mf][nf], aL, bH);
                    mma_bf16(acc[mf][nf], aH, bL);
                    mma_bf16(acc[mf][nf], aH, bH);
                }
            }
        }
        __syncthreads();
    }

#pragma unroll
    for (int mf = 0; mf < 2; mf++)
#pragma unroll
        for (int nf = 0; nf < 4; nf++)
#pragma unroll
            for (int ci = 0; ci < 4; ci++) {
                int m = bm0 + wm0 + mf * 16 + lq + ((ci >= 2) ? 8 : 0);
                int n = bn0 + wn0 + nf * 8 + lr * 2 + (ci & 1);
                if (m >= M || n >= N) continue;
                float v = acc[mf][nf][ci] + (bias ? bias[n] : 0.f);
                if (EPI == 1) v = fmaxf(v, 0.f);
                else if (EPI == 2) v = 1.f / (1.f + expf(-v));
                else if (EPI == 3) v = tanhf(v);
                C[(size_t)m * N + n] = v;
            }
}

// ================== wide GEMM: BM=64 BN=128, warp tile 32x64 =================
template <int EPI>   // 0 none, 1 relu
__global__ __launch_bounds__(128, 2)
void bf_gemm_w(const float* __restrict__ A, const float* __restrict__ B,
               const float* __restrict__ bias, float* __restrict__ C,
               int M, int N, int K, int kSplit) {
    __shared__ __align__(16) unsigned char sm[24576];
    uint32_t sbase = (uint32_t)__cvta_generic_to_shared(sm);

    int bn0 = blockIdx.x * 128, bm0 = blockIdx.y * 64;
    int kS = blockIdx.z * kSplit;
    C += (size_t)blockIdx.z * M * N;

    int tid = threadIdx.x, warp = tid >> 5, lane = tid & 31;
    int wm0 = (warp & 1) * 32, wn0 = (warp >> 1) * 64;
    int lq = lane >> 2, lr = lane & 3;

    int aM[2], aG[2];
#pragma unroll
    for (int u = 0; u < 2; u++) {
        int e = tid + 128 * u;
        aM[u] = e >> 2; aG[u] = e & 3;
    }
    int bKr[4], bC[4];
#pragma unroll
    for (int u = 0; u < 4; u++) {
        int e = tid + 128 * u;
        bKr[u] = e >> 4; bC[u] = e & 15;
    }

    int matSel = lane >> 3;
    int rowA = (lane & 7) + ((matSel & 1) << 3);
    int cbitA = matSel >> 1;
    int rA0 = wm0 + rowA, rA1 = wm0 + 16 + rowA;
    int swzA0 = (rA0 >> 1) & 3, swzA1 = (rA1 >> 1) & 3;
    uint32_t aRow0 = sbase + rA0 * 64;
    uint32_t aRow1 = sbase + rA1 * 64;

    int kr0 = (lane & 7) + ((matSel & 1) << 3);
    int msHalf = matSel >> 1;
    uint32_t bOffG[4];
#pragma unroll
    for (int g = 0; g < 4; g++) {
        int cb = (wn0 >> 3) + 2 * g + msHalf;
        bOffG[g] = sbase + 8192 + kr0 * 256 + ((uint32_t)(cb ^ (kr0 & 7)) << 4);
    }

    float acc[2][8][4];
#pragma unroll
    for (int i = 0; i < 2; i++)
#pragma unroll
        for (int j = 0; j < 8; j++)
#pragma unroll
            for (int k = 0; k < 4; k++) acc[i][j][k] = 0.f;

    float4 pa[2][2], pb[4][2];
    const float4 z4 = make_float4(0.f, 0.f, 0.f, 0.f);

    auto loadTile = [&](int t) {
#pragma unroll
        for (int u = 0; u < 2; u++) {
            int gm = bm0 + aM[u];
            int ka = kS + t * 32 + aG[u] * 8;
            if (gm < M) {
                const float* p = A + (size_t)gm * K + ka;
                pa[u][0] = *(const float4*)p; pa[u][1] = *(const float4*)(p + 4);
            } else { pa[u][0] = z4; pa[u][1] = z4; }
        }
#pragma unroll
        for (int u = 0; u < 4; u++) {
            int gn = bn0 + bC[u] * 8;
            int kb = kS + t * 32 + bKr[u];
            if (gn < N) {
                const float* p = B + (size_t)kb * N + gn;
                pb[u][0] = *(const float4*)p; pb[u][1] = *(const float4*)(p + 4);
            } else { pb[u][0] = z4; pb[u][1] = z4; }
        }
    };

    loadTile(0);
    int T = kSplit / 32;
    for (int t = 0; t < T; t++) {
#pragma unroll
        for (int u = 0; u < 2; u++) {
            uint4 hi, lo;
            cvt8(pa[u][0], pa[u][1], hi, lo);
            uint32_t off = aM[u] * 64 + ((uint32_t)(aG[u] ^ ((aM[u] >> 1) & 3)) << 4);
            *(uint4*)(sm + off) = hi;
            *(uint4*)(sm + 4096 + off) = lo;
        }
#pragma unroll
        for (int u = 0; u < 4; u++) {
            uint4 hi, lo;
            cvt8(pb[u][0], pb[u][1], hi, lo);
            uint32_t off = 8192 + bKr[u] * 256 + ((uint32_t)(bC[u] ^ (bKr[u] & 7)) << 4);
            *(uint4*)(sm + off) = hi;
            *(uint4*)(sm + 8192 + off) = lo;
        }
        __syncthreads();

        if (t + 1 < T) loadTile(t + 1);

#pragma unroll
        for (int s = 0; s < 2; s++) {
            uint32_t aH0[4], aL0[4], aH1[4], aL1[4];
            uint32_t ad0 = aRow0 + ((uint32_t)((2 * s + cbitA) ^ swzA0) << 4);
            uint32_t ad1 = aRow1 + ((uint32_t)((2 * s + cbitA) ^ swzA1) << 4);
            ldsm4(aH0, ad0); ldsm4(aL0, ad0 + 4096);
            ldsm4(aH1, ad1); ldsm4(aL1, ad1 + 4096);
            uint32_t bH[4][4], bL[4][4];
#pragma unroll
            for (int g = 0; g < 4; g++) {
                uint32_t bd = bOffG[g] + s * 4096;
                ldsm4t(bH[g], bd);
                ldsm4t(bL[g], bd + 8192);
            }
#pragma unroll
            for (int mf = 0; mf < 2; mf++) {
                const uint32_t* aH = mf ? aH1 : aH0;
                const uint32_t* aL = mf ? aL1 : aL0;
#pragma unroll
                for (int nf = 0; nf < 8; nf++) {
                    int g = nf >> 1;
                    const uint32_t* pbH = &bH[g][(nf & 1) * 2];
                    const uint32_t* pbL = &bL[g][(nf & 1) * 2];
                    mma_bf16(acc[mf][nf], aL, pbH);
                    mma_bf16(acc[mf][nf], aH, pbL);
                    mma_bf16(acc[mf][nf], aH, pbH);
                }
            }
        }
        __syncthreads();
    }

#pragma unroll
    for (int mf = 0; mf < 2; mf++)
#pragma unroll
        for (int nf = 0; nf < 8; nf++)
#pragma unroll
            for (int ci = 0; ci < 4; ci++) {
                int m = bm0 + wm0 + mf * 16 + lq + ((ci >= 2) ? 8 : 0);
                int n = bn0 + wn0 + nf * 8 + lr * 2 + (ci & 1);
                if (m >= M || n >= N) continue;
                float v = acc[mf][nf][ci] + (bias ? bias[n] : 0.f);
                if (EPI == 1) v = fmaxf(v, 0.f);
                C[(size_t)m * N + n] = v;
            }
}

// ---------------- w1 row permutation ------------------------------------------
__global__ __launch_bounds__(256)
void permute_w1_kernel(const float* __restrict__ w1, float* __restrict__ w1p) {
    int k = blockIdx.x;
    int d = k / 49, bin = k - d * 49;
    int kp = bin * 64 + d;
    w1p[(size_t)kp * 256 + threadIdx.x] = w1[(size_t)k * 256 + threadIdx.x];
}

// ---------------- generic split-K combine: H = epi(sum_z P_z + bias) ----------
template <int EPI, int Z>
__global__ __launch_bounds__(256)
void combine_k(const float* __restrict__ P, const float* __restrict__ bias,
               float* __restrict__ H, int total, int nMask) {
    int i = blockIdx.x * 256 + threadIdx.x;
    if (i < total) {
        float v = bias[i & nMask];
#pragma unroll
        for (int z = 0; z < Z; z++)
            v += P[(size_t)z * total + i];
        if (EPI == 1) v = fmaxf(v, 0.f);
        else if (EPI == 3) v = tanhf(v);
        H[i] = v;
    }
}

// ---------------- build X rows (round-13 proven) ------------------------------
__global__ __launch_bounds__(256)
void build_x_kernel(const float* __restrict__ ref, const float* __restrict__ p1_b) {
    int blk = blockIdx.x;                 // lvl*600 + b*300 + q
    int lvl = blk / BQ;
    int rem = blk - lvl * BQ;
    int b = rem / NQ;
    int q = rem - b * NQ;
    int W = c_dim[lvl];
    int start = c_start[lvl];
    const float* r6 = ref + ((size_t)(b * NQ + q) * LVLS + lvl) * 6;
    float sx, sy, bw, bh;
    box_geom(r6, W, sx, sy, bw, bh);

    __shared__ float2 sWI[196][4];        // {weight, idx-as-int bits}
    int tid = threadIdx.x;
    if (tid < 196) {
        int si = tid / 14, sj = tid - si * 14;
        int idx4[4]; float wt4[4];
        sample4(sx, sy, bw, bh, W, si, sj, idx4, wt4);
#pragma unroll
        for (int k = 0; k < 4; k++)
            sWI[tid][k] = make_float2(wt4[k], __int_as_float(idx4[k]));
    }
    __syncthreads();

    int sub = tid >> 4;                    // 0..15 (bin subgroup)
    int d4  = (tid & 15) * 4;              // channel base
    const float* projB = g_proj + ((size_t)b * TOTALPIX + start) * 64 + d4;
    float4 bias4 = *(const float4*)(p1_b + d4);
    float* Xrow = g_X + (size_t)blk * XCOLS;
    for (int bin = sub; bin < 49; bin += 16) {
        int h = bin / 7, w_ = bin - h * 7;
        float4 acc = make_float4(0.f, 0.f, 0.f, 0.f);
#pragma unroll
        for (int s2 = 0; s2 < 4; s2++) {
            int s = (2 * h + (s2 >> 1)) * 14 + 2 * w_ + (s2 & 1);
#pragma unroll
            for (int cr = 0; cr < 4; cr++) {
                float2 wi = sWI[s][cr];
                float w = wi.x;
                int idx = __float_as_int(wi.y);
                const float4 v = *(const float4*)(projB + (size_t)idx * 64);
                acc.x += w * v.x; acc.y += w * v.y;
                acc.z += w * v.z; acc.w += w * v.w;
            }
        }
        float4 o;
        o.x = fmaxf(acc.x + bias4.x, 0.f);
        o.y = fmaxf(acc.y + bias4.y, 0.f);
        o.z = fmaxf(acc.z + bias4.z, 0.f);
        o.w = fmaxf(acc.w + bias4.w, 0.f);
        *(float4*)(Xrow + bin * 64 + d4) = o;
    }
}

// ---------------- finalize: inline pts combine + dedup/compact gathers -------
__global__ __launch_bounds__(256)
void finalize_kernel(const float* __restrict__ memory, const float* __restrict__ ref,
                     const float* __restrict__ P4, const float* __restrict__ b4,
                     const float* __restrict__ a2w, const float* __restrict__ a2b,
                     float* __restrict__ out) {
    int bq = blockIdx.x;                   // b*300 + q
    int b = bq / NQ;
    int tid = threadIdx.x;

    __shared__ float qe_s[32][HIDDEN];     // 32 KB
    __shared__ float wArr[2048];           // 8 KB
    __shared__ unsigned short iArr[2048];  // 4 KB
    __shared__ unsigned short cntArr[64];
    __shared__ float sPts[64];             // (lvl,head) x {gx,gy}
    __shared__ float logits[32];
    __shared__ float wgt[32];

    // inline pts split-K combine: pts = tanh(b4 + sum_z P_z), rows lvl*BQ+bq
    if (tid < 64) {
        int lvl = tid >> 4;                // 0..3
        int col = tid & 15;                // 0..15 = 2*head + coord
        int row = lvl * BQ + bq;
        float v = b4[col];
#pragma unroll
        for (int z = 0; z < 4; z++)
            v += P4[(size_t)z * NROWS * 16 + (size_t)row * 16 + col];
        sPts[tid] = tanhf(v);
    }
    __syncthreads();

    for (int e = tid; e < 2048; e += 256) {
        int lvl = e >> 9;
        int head = (e >> 6) & 7;
        int bc = (e >> 4) & 3;
        int sm = (e >> 2) & 3;
        int cr = e & 3;
        int W = c_dim[lvl];
        int start = c_start[lvl];
        const float* r6 = ref + ((size_t)bq * LVLS + lvl) * 6;
        float sx, sy, bw, bh;
        box_geom(r6, W, sx, sy, bw, bh);

        float gx = sPts[lvl * 16 + 2 * head];
        float gy = sPts[lvl * 16 + 2 * head + 1];
        float ix = ((gx + 1.f) * 7.f - 1.f) * 0.5f;
        float iy = ((gy + 1.f) * 7.f - 1.f) * 0.5f;
        float bxf = floorf(ix), byf = floorf(iy);
        float lx = ix - bxf, ly = iy - byf;
        int dby = bc >> 1, dbx = bc & 1;
        int bi = (int)byf + dby, bj = (int)bxf + dbx;
        float wb = (dby ? ly : 1.f - ly) * (dbx ? lx : 1.f - lx);
        if (bi < 0 || bi > 6 || bj < 0 || bj > 6) wb = 0.f;
        int si = 2 * bi + (sm >> 1);
        int sj = 2 * bj + (sm & 1);
        int idx4[4]; float wt4[4];
        sample4(sx, sy, bw, bh, W, si, sj, idx4, wt4);
        wArr[e] = wb * wt4[cr];
        iArr[e] = (unsigned short)(b * TOTALPIX + start + idx4[cr]);
    }
    __syncthreads();

    // dedup + compact per 32-entry half of each (lvl,head) group
    {
        int warp = tid >> 5, lane = tid & 31;
        for (int h = warp; h < 64; h += 8) {
            int e = h * 32 + lane;
            unsigned idx = iArr[e];
            float w = wArr[e];
            unsigned mask = __match_any_sync(0xffffffffu, idx);
            int leader = __ffs(mask) - 1;
            float tot = 0.f;
#pragma unroll
            for (int bb = 0; bb < 32; bb++) {
                float wb2 = __shfl_sync(0xffffffffu, w, bb);
                if ((mask >> bb) & 1) tot += wb2;
            }
            float wn = (lane == leader) ? tot : 0.f;
            unsigned bal = __ballot_sync(0xffffffffu, wn != 0.f);
            int pos = __popc(bal & ((1u << lane) - 1));
            if (wn != 0.f) {
                wArr[h * 32 + pos] = wn;
                iArr[h * 32 + pos] = (unsigned short)idx;
            }
            if (lane == 0) cntArr[h] = (unsigned short)__popc(bal);
        }
    }
    __syncthreads();

    const float* gateRow = g_gate + (size_t)bq * (NHEADS * HIDDEN);
    int g64 = tid >> 6;                    // 0..3
    int c4 = (tid & 63) * 4;               // channel base
    for (int lh = g64; lh < 32; lh += 4) {
        float4 acc = make_float4(0.f, 0.f, 0.f, 0.f);
        int eb = lh << 6;
        int n0 = cntArr[2 * lh], n1 = cntArr[2 * lh + 1];
        for (int e = 0; e < n0; e++) {
            float w = wArr[eb + e];
            const float4 v = *(const float4*)(memory + (size_t)iArr[eb + e] * HIDDEN + c4);
            acc.x += w * v.x; acc.y += w * v.y;
            acc.z += w * v.z; acc.w += w * v.w;
        }
        for (int e = 0; e < n1; e++) {
            float w = wArr[eb + 32 + e];
            const float4 v = *(const float4*)(memory + (size_t)iArr[eb + 32 + e] * HIDDEN + c4);
            acc.x += w * v.x; acc.y += w * v.y;
            acc.z += w * v.z; acc.w += w * v.w;
        }
        const float4 gt = *(const float4*)(gateRow + (lh & 7) * HIDDEN + c4);
        qe_s[lh][c4 + 0] = acc.x * gt.x;
        qe_s[lh][c4 + 1] = acc.y * gt.y;
        qe_s[lh][c4 + 2] = acc.z * gt.z;
        qe_s[lh][c4 + 3] = acc.w * gt.w;
    }
    __syncthreads();

    int warp = tid >> 5, lane = tid & 31;
    for (int r = warp; r < 32; r += 8) {
        float s = 0.f;
#pragma unroll
        for (int c2 = lane; c2 < HIDDEN; c2 += 32) s += qe_s[r][c2] * a2w[c2];
#pragma unroll
        for (int o = 16; o; o >>= 1) s += __shfl_xor_sync(0xffffffffu, s, o);
        if (lane == 0) logits[r] = s + a2b[0];
    }
    __syncthreads();

    if (tid < 32) {
        float l = logits[tid];
        float mx = l;
#pragma unroll
        for (int o = 16; o; o >>= 1) mx = fmaxf(mx, __shfl_xor_sync(0xffffffffu, mx, o));
        float ex = expf(l - mx);
        float sum = ex;
#pragma unroll
        for (int o = 16; o; o >>= 1) sum += __shfl_xor_sync(0xffffffffu, sum, o);
        wgt[tid] = ex / sum;
    }
    __syncthreads();

    int c = tid;
    float o = 0.f;
#pragma unroll
    for (int r = 0; r < 32; r++) o += wgt[r] * qe_s[r][c];
    out[(size_t)bq * HIDDEN + c] = o;
}

// -----------------------------------------------------------------------------
static inline int cdiv(int a, int b) { return (a + b - 1) / b; }

extern "C" void kernel_launch(void* const* d_in, const int* in_sizes, int n_in,
                              void* d_out, int out_size) {
    const float* tgt    = (const float*)d_in[0];
    const float* memory = (const float*)d_in[1];
    const float* ref    = (const float*)d_in[2];
    const float* p1_w = (const float*)d_in[4];
    const float* p1_b = (const float*)d_in[5];
    const float* w1   = (const float*)d_in[6];
    const float* b1   = (const float*)d_in[7];
    const float* w2   = (const float*)d_in[8];
    const float* b2   = (const float*)d_in[9];
    const float* w3   = (const float*)d_in[10];
    const float* b3   = (const float*)d_in[11];
    const float* w4   = (const float*)d_in[12];
    const float* b4   = (const float*)d_in[13];
    const float* a1w  = (const float*)d_in[14];
    const float* a1b  = (const float*)d_in[15];
    const float* a2w  = (const float*)d_in[16];
    const float* a2b  = (const float*)d_in[17];
    float* out = (float*)d_out;

    float *gate, *proj, *X, *w1p, *P, *H1, *H2;
    cudaGetSymbolAddress((void**)&gate, g_gate);
    cudaGetSymbolAddress((void**)&proj, g_proj);
    cudaGetSymbolAddress((void**)&X,    g_X);
    cudaGetSymbolAddress((void**)&w1p,  g_w1p);
    cudaGetSymbolAddress((void**)&P,    g_P);
    cudaGetSymbolAddress((void**)&H1,   g_H1);
    cudaGetSymbolAddress((void**)&H2,   g_H2);

    dim3 t(128);
    // w1 row permutation (independent)
    permute_w1_kernel<<<XCOLS, 256>>>(w1, w1p);
    // gate = sigmoid(tgt @ attn1_w + attn1_b)   (600 x 2048, K=256)
    bf_gemm<2, 0><<<dim3(32, 10, 1), t>>>(tgt, nullptr, nullptr, a1w, a1b, gate,
                                          BQ, 2048, 256, 256);
    // proj = memory @ p1_w                       (43520 x 64, K=256)
    bf_gemm<0, 0><<<dim3(1, 680, 1), t>>>(memory, nullptr, nullptr, p1_w, nullptr, proj,
                                          BS * TOTALPIX, 64, 256, 256);
    // X rows via roi_align on projected memory (permuted col layout)
    build_x_kernel<<<NROWS, 256>>>(ref, p1_b);
    // MLP layer 1: WIDE tiles + split-K=7 (slabs of 448), then combine
    bf_gemm_w<0><<<dim3(2, 38, KSPLIT1), t>>>(X, w1p, nullptr, P, NROWS, 256, XCOLS, 448);
    combine_k<1, KSPLIT1><<<cdiv(NROWS * 256, 256), 256>>>(P, b1, H1, NROWS * 256, 255);
    // MLP layer 2: WIDE with fused bias+relu
    bf_gemm_w<1><<<dim3(4, 38, 1), t>>>(H1, w2, b2, H2, NROWS, 512, 256, 256);
    // MLP layer 3: WIDE split-K=2, partials in P (combine fused into pts loader)
    bf_gemm_w<0><<<dim3(4, 38, 2), t>>>(H2, w3, nullptr, P, NROWS, 512, 512, 256);
    // MLP layer 4 (pts): narrow, A = relu(b3 + P0 + P1) fused; split-K=4 -> H1 buf
    bf_gemm<0, 1><<<dim3(1, 38, 4), t>>>(P, P + (size_t)NROWS * 512, b3, w4, nullptr, H1,
                                         NROWS, 16, 512, 128);
    // grid-sample recompute + inline pts combine + gate + softmax combine
    finalize_kernel<<<BQ, 256>>>(memory, ref, H1, b4, a2w, a2b, out);
}